// round 12
// baseline (speedup 1.0000x reference)
#include <cuda_runtime.h>
#include <cuda_fp16.h>
#include <cstdint>

// Problem constants
#define N_  8192
#define M_  8192
#define D_  64
#define H_  32
#define T_  8

#define TTM    256                      // X rows per row-tile
#define TTN    128                      // Y rows per tile
#define NRT    (N_ / TTM)               // 32 row-tiles
#define NYT    (M_ / TTN)               // 64 Y-tiles
#define NITEMS (NRT * NYT)              // 2048 work items
#define NCTA   148                      // persistent CTAs (one per SM)
#define THREADS 512
#define LOG2E     1.4426950408889634f
#define HALF_L2E  0.7213475204444817f

typedef unsigned long long u64;
typedef unsigned int u32;

// ---------------- global scratch ----------------
__device__ __half g_Fhi[(N_ + M_) * H_];   // X rows pre-scaled by log2e; Y rows raw
__device__ __half g_Flo[(N_ + M_) * H_];
__device__ float  g_Fn[N_ + M_];           // -0.5*log2e*||f||^2
__device__ __half g_Vhi[M_ * T_];          // Yt hi, [j][t]
__device__ __half g_Vlo[M_ * T_];
// run partials: [cta*2+run][t(0..8)][rloc(0..255)]
__device__ float  g_partR[NCTA * 2 * (T_ + 1) * TTM];
#define IDXR(slot, t, rloc) ((((slot) * (T_ + 1)) + (t)) * TTM + (rloc))

__device__ __forceinline__ int item_lo(int c) { return (c * NITEMS) / NCTA; }

// ---------------- helpers ----------------
__device__ __forceinline__ u32 smem_u32(const void* p) {
    u32 a; asm("{ .reg .u64 t; cvta.to.shared.u64 t, %1; cvt.u32.u64 %0, t; }" : "=r"(a) : "l"(p));
    return a;
}
__device__ __forceinline__ float ex2f(float x) {
    float r; asm("ex2.approx.ftz.f32 %0, %1;" : "=f"(r) : "f"(x)); return r;
}
__device__ __forceinline__ void ldmx4(u32& r0, u32& r1, u32& r2, u32& r3, u32 addr) {
    asm volatile("ldmatrix.sync.aligned.m8n8.x4.shared.b16 {%0,%1,%2,%3}, [%4];"
        : "=r"(r0), "=r"(r1), "=r"(r2), "=r"(r3) : "r"(addr));
}
__device__ __forceinline__ void ldmx2t(u32& r0, u32& r1, u32 addr) {
    asm volatile("ldmatrix.sync.aligned.m8n8.x2.trans.shared.b16 {%0,%1}, [%2];"
        : "=r"(r0), "=r"(r1) : "r"(addr));
}
__device__ __forceinline__ void mma16816(float& c0, float& c1, float& c2, float& c3,
                                         u32 a0, u32 a1, u32 a2, u32 a3, u32 b0, u32 b1) {
    asm volatile("mma.sync.aligned.m16n8k16.row.col.f32.f16.f16.f32 "
        "{%0,%1,%2,%3},{%4,%5,%6,%7},{%8,%9},{%0,%1,%2,%3};"
        : "+f"(c0), "+f"(c1), "+f"(c2), "+f"(c3)
        : "r"(a0), "r"(a1), "r"(a2), "r"(a3), "r"(b0), "r"(b1));
}
__device__ __forceinline__ u32 packh2(float a, float b) {
    __half2 h = __floats2half2_rn(a, b);
    return *(u32*)&h;
}

// ---------------- dist SMEM layout ----------------
#define PITCH   80                      // 64B data + 16B pad -> conflict-free ldmatrix
#define S_AHI   0                       // 256 rows * 80B
#define S_ALO   20480
#define S_B     40960                   // [stage][hi/lo]: stage*20480, lo +10240
#define S_V     81920                   // [stage][hi/lo]: stage*4096, lo +2048
#define S_CY    90112                   // [stage] 512B
#define SMEM_TOTAL 91136

// ---------------- mlp2 SMEM layout (64 rows per CTA) ----------------
#define XP      144                     // X row pitch bytes (128B data + 16 pad)
#define M2_FH   0                       // 64*144 = 9216
#define M2_FL   9216
#define M2_WH   18432                   // 128 rows (W1:0-63, W2:64-95, W3:96-127) * 80B
#define M2_WL   28672
#define M2_BI   38912                   // 96 floats
#define M2_TOTAL 39296

// ---------------- kernel 1: MLP on tensor cores (64 rows/CTA) + fused V prep ----------------
#define MLP2BLKS ((N_ + M_) / 64)       // 256
__global__ __launch_bounds__(128)
void mlp2_kernel(const float* __restrict__ X, const float* __restrict__ Y,
                 const float* __restrict__ Yt,
                 const float* __restrict__ W1, const float* __restrict__ b1,
                 const float* __restrict__ W2, const float* __restrict__ b2,
                 const float* __restrict__ W3, const float* __restrict__ b3)
{
    if (blockIdx.x >= MLP2BLKS) {           // tail blocks: build V hi/lo
        int idx = (blockIdx.x - MLP2BLKS) * 128 + threadIdx.x;  // M_*T_
        float v = Yt[idx];
        __half hi = __float2half_rn(v);
        g_Vhi[idx] = hi;
        g_Vlo[idx] = __float2half_rn(v - __half2float(hi));
        return;
    }

    extern __shared__ char smem[];
    u32 sb = smem_u32(smem);
    int tid = threadIdx.x, w = tid >> 5, l = tid & 31;
    int g = l >> 2, tig = l & 3;
    int row0 = blockIdx.x * 64;
    bool isX = (row0 < N_);
    const float* src = isX ? (X + (size_t)row0 * D_) : (Y + (size_t)(row0 - N_) * D_);

    // ---- load X tile [64 x 64] f32 -> hi/lo f16, pitch 144B
#pragma unroll
    for (int q = 0; q < 8; q++) {
        int idx = q * 128 + tid;            // 1024 float4
        int r = idx >> 4, c4 = idx & 15;
        float4 v = ((const float4*)src)[idx];
        float hx = __half2float(__float2half_rn(v.x));
        float hy = __half2float(__float2half_rn(v.y));
        float hz = __half2float(__float2half_rn(v.z));
        float hw = __half2float(__float2half_rn(v.w));
        u32* ph = (u32*)(smem + M2_FH + r * XP + c4 * 8);
        u32* pl = (u32*)(smem + M2_FL + r * XP + c4 * 8);
        ph[0] = packh2(v.x, v.y);        ph[1] = packh2(v.z, v.w);
        pl[0] = packh2(v.x - hx, v.y - hy); pl[1] = packh2(v.z - hz, v.w - hw);
    }
    // ---- weights [k][n] hi/lo, pitch 80B. W1 rows 0-63, W2 64-95, W3 96-127
#pragma unroll
    for (int q = 0; q < 4; q++) {           // W1: 512 float4
        int idx = q * 128 + tid;
        int r = idx >> 3, c4 = idx & 7;
        float4 v = ((const float4*)W1)[idx];
        float hx = __half2float(__float2half_rn(v.x));
        float hy = __half2float(__float2half_rn(v.y));
        float hz = __half2float(__float2half_rn(v.z));
        float hw = __half2float(__float2half_rn(v.w));
        u32* ph = (u32*)(smem + M2_WH + r * PITCH + c4 * 8);
        u32* pl = (u32*)(smem + M2_WL + r * PITCH + c4 * 8);
        ph[0] = packh2(v.x, v.y);        ph[1] = packh2(v.z, v.w);
        pl[0] = packh2(v.x - hx, v.y - hy); pl[1] = packh2(v.z - hz, v.w - hw);
    }
    {                                        // W2 + W3: 256+256 float4
        const float4* Wsrc[2] = { (const float4*)W2, (const float4*)W3 };
#pragma unroll
        for (int m = 0; m < 2; m++) {
#pragma unroll
            for (int q = 0; q < 2; q++) {
                int idx = q * 128 + tid;
                int r = 64 + m * 32 + (idx >> 3), c4 = idx & 7;
                float4 v = Wsrc[m][idx];
                float hx = __half2float(__float2half_rn(v.x));
                float hy = __half2float(__float2half_rn(v.y));
                float hz = __half2float(__float2half_rn(v.z));
                float hw = __half2float(__float2half_rn(v.w));
                u32* ph = (u32*)(smem + M2_WH + r * PITCH + c4 * 8);
                u32* pl = (u32*)(smem + M2_WL + r * PITCH + c4 * 8);
                ph[0] = packh2(v.x, v.y);        ph[1] = packh2(v.z, v.w);
                pl[0] = packh2(v.x - hx, v.y - hy); pl[1] = packh2(v.z - hz, v.w - hw);
            }
        }
    }
    if (tid < 96) {
        float bv = (tid < 32) ? b1[tid] : (tid < 64) ? b2[tid - 32] : b3[tid - 64];
        ((float*)(smem + M2_BI))[tid] = bv;
    }
    __syncthreads();

    const float* sbias = (const float*)(smem + M2_BI);

    // ---- A frags from X (4 k-steps)
    u32 aH[4][4], aL[4][4];
    {
        u32 arow = (u32)(w * 16 + (l & 15)) * XP + (u32)(l >> 4) * 16;
#pragma unroll
        for (int ks = 0; ks < 4; ks++) {
            ldmx4(aH[ks][0], aH[ks][1], aH[ks][2], aH[ks][3], sb + M2_FH + arow + ks * 32);
            ldmx4(aL[ks][0], aL[ks][1], aL[ks][2], aL[ks][3], sb + M2_FL + arow + ks * 32);
        }
    }
    u32 brow = (u32)(l & 15) * PITCH;

    // ---- layer 1
    u32 h1H[2][4], h1L[2][4];
#pragma unroll
    for (int nc = 0; nc < 4; nc++) {
        float cA[4] = {0,0,0,0}, cB[4] = {0,0,0,0}, cC[4] = {0,0,0,0};
#pragma unroll
        for (int ks = 0; ks < 4; ks++) {
            u32 woff = (u32)(ks * 16) * PITCH + (u32)nc * 16 + brow;
            u32 wh0, wh1, wl0, wl1;
            ldmx2t(wh0, wh1, sb + M2_WH + woff);
            ldmx2t(wl0, wl1, sb + M2_WL + woff);
            mma16816(cA[0],cA[1],cA[2],cA[3], aH[ks][0],aH[ks][1],aH[ks][2],aH[ks][3], wh0, wh1);
            mma16816(cB[0],cB[1],cB[2],cB[3], aH[ks][0],aH[ks][1],aH[ks][2],aH[ks][3], wl0, wl1);
            mma16816(cC[0],cC[1],cC[2],cC[3], aL[ks][0],aL[ks][1],aL[ks][2],aL[ks][3], wh0, wh1);
        }
        float b0 = sbias[nc * 8 + 2 * tig], b1v = sbias[nc * 8 + 2 * tig + 1];
        float v0 = fmaxf(cA[0] + cB[0] + cC[0] + b0,  0.f);
        float v1 = fmaxf(cA[1] + cB[1] + cC[1] + b1v, 0.f);
        float v2 = fmaxf(cA[2] + cB[2] + cC[2] + b0,  0.f);
        float v3 = fmaxf(cA[3] + cB[3] + cC[3] + b1v, 0.f);
        u32 h01 = packh2(v0, v1), h23 = packh2(v2, v3);
        float2 f01 = __half22float2(*(__half2*)&h01), f23 = __half22float2(*(__half2*)&h23);
        int ks2 = nc >> 1, pos = (nc & 1) * 2;
        h1H[ks2][pos] = h01; h1H[ks2][pos + 1] = h23;
        h1L[ks2][pos]     = packh2(v0 - f01.x, v1 - f01.y);
        h1L[ks2][pos + 1] = packh2(v2 - f23.x, v3 - f23.y);
    }

    // ---- layer 2
    u32 h2H[2][4], h2L[2][4];
#pragma unroll
    for (int nc = 0; nc < 4; nc++) {
        float cA[4] = {0,0,0,0}, cB[4] = {0,0,0,0}, cC[4] = {0,0,0,0};
#pragma unroll
        for (int ks = 0; ks < 2; ks++) {
            u32 woff = (u32)(64 + ks * 16) * PITCH + (u32)nc * 16 + brow;
            u32 wh0, wh1, wl0, wl1;
            ldmx2t(wh0, wh1, sb + M2_WH + woff);
            ldmx2t(wl0, wl1, sb + M2_WL + woff);
            mma16816(cA[0],cA[1],cA[2],cA[3], h1H[ks][0],h1H[ks][1],h1H[ks][2],h1H[ks][3], wh0, wh1);
            mma16816(cB[0],cB[1],cB[2],cB[3], h1H[ks][0],h1H[ks][1],h1H[ks][2],h1H[ks][3], wl0, wl1);
            mma16816(cC[0],cC[1],cC[2],cC[3], h1L[ks][0],h1L[ks][1],h1L[ks][2],h1L[ks][3], wh0, wh1);
        }
        float b0 = sbias[32 + nc * 8 + 2 * tig], b1v = sbias[32 + nc * 8 + 2 * tig + 1];
        float v0 = fmaxf(cA[0] + cB[0] + cC[0] + b0,  0.f);
        float v1 = fmaxf(cA[1] + cB[1] + cC[1] + b1v, 0.f);
        float v2 = fmaxf(cA[2] + cB[2] + cC[2] + b0,  0.f);
        float v3 = fmaxf(cA[3] + cB[3] + cC[3] + b1v, 0.f);
        u32 h01 = packh2(v0, v1), h23 = packh2(v2, v3);
        float2 f01 = __half22float2(*(__half2*)&h01), f23 = __half22float2(*(__half2*)&h23);
        int ks2 = nc >> 1, pos = (nc & 1) * 2;
        h2H[ks2][pos] = h01; h2H[ks2][pos + 1] = h23;
        h2L[ks2][pos]     = packh2(v0 - f01.x, v1 - f01.y);
        h2L[ks2][pos + 1] = packh2(v2 - f23.x, v3 - f23.y);
    }

    // ---- layer 3 + epilogue
    float nxA = 0.f, nxB = 0.f;
    int rg = row0 + w * 16 + g;
    float sc = isX ? LOG2E : 1.f;
#pragma unroll
    for (int nc = 0; nc < 4; nc++) {
        float cA[4] = {0,0,0,0}, cB[4] = {0,0,0,0}, cC[4] = {0,0,0,0};
#pragma unroll
        for (int ks = 0; ks < 2; ks++) {
            u32 woff = (u32)(96 + ks * 16) * PITCH + (u32)nc * 16 + brow;
            u32 wh0, wh1, wl0, wl1;
            ldmx2t(wh0, wh1, sb + M2_WH + woff);
            ldmx2t(wl0, wl1, sb + M2_WL + woff);
            mma16816(cA[0],cA[1],cA[2],cA[3], h2H[ks][0],h2H[ks][1],h2H[ks][2],h2H[ks][3], wh0, wh1);
            mma16816(cB[0],cB[1],cB[2],cB[3], h2H[ks][0],h2H[ks][1],h2H[ks][2],h2H[ks][3], wl0, wl1);
            mma16816(cC[0],cC[1],cC[2],cC[3], h2L[ks][0],h2L[ks][1],h2L[ks][2],h2L[ks][3], wh0, wh1);
        }
        float b0 = sbias[64 + nc * 8 + 2 * tig], b1v = sbias[64 + nc * 8 + 2 * tig + 1];
        float v0 = fmaxf(cA[0] + cB[0] + cC[0] + b0,  0.f);
        float v1 = fmaxf(cA[1] + cB[1] + cC[1] + b1v, 0.f);
        float v2 = fmaxf(cA[2] + cB[2] + cC[2] + b0,  0.f);
        float v3 = fmaxf(cA[3] + cB[3] + cC[3] + b1v, 0.f);
        nxA += v0 * v0 + v1 * v1;
        nxB += v2 * v2 + v3 * v3;
        float s0 = v0 * sc, s1 = v1 * sc, s2 = v2 * sc, s3 = v3 * sc;
        u32 h01 = packh2(s0, s1), h23 = packh2(s2, s3);
        float2 f01 = __half22float2(*(__half2*)&h01), f23 = __half22float2(*(__half2*)&h23);
        u32 l01 = packh2(s0 - f01.x, s1 - f01.y), l23 = packh2(s2 - f23.x, s3 - f23.y);
        ((u32*)g_Fhi)[rg * 16 + nc * 4 + tig]       = h01;
        ((u32*)g_Fhi)[(rg + 8) * 16 + nc * 4 + tig] = h23;
        ((u32*)g_Flo)[rg * 16 + nc * 4 + tig]       = l01;
        ((u32*)g_Flo)[(rg + 8) * 16 + nc * 4 + tig] = l23;
    }
    nxA += __shfl_xor_sync(0xffffffffu, nxA, 1);
    nxA += __shfl_xor_sync(0xffffffffu, nxA, 2);
    nxB += __shfl_xor_sync(0xffffffffu, nxB, 1);
    nxB += __shfl_xor_sync(0xffffffffu, nxB, 2);
    if (tig == 0) {
        g_Fn[rg]     = -HALF_L2E * nxA;
        g_Fn[rg + 8] = -HALF_L2E * nxB;
    }
}

// ---------------- kernel 2: persistent HMMA flash kernel (148 CTAs) ----------------
__global__ __launch_bounds__(THREADS)
void dist_kernel()
{
    extern __shared__ char smem[];
    u32 sb = smem_u32(smem);
    int tid = threadIdx.x, w = tid >> 5, l = tid & 31;
    int g = l >> 2, tig = l & 3;
    int c = blockIdx.x;
    int s_c = item_lo(c), e_c = item_lo(c + 1);

    u32 bArow = (u32)(l & 7) * PITCH + (u32)(l >> 3) * 16;
    u32 vArow = (u32)(l & 15) * 16;
    u32 arow  = (u32)(w * 16 + (l & 15)) * PITCH + (u32)(l >> 4) * 16;

    u32 aH0[4], aH1[4], aL0[4], aL1[4];
    float cx0 = 0.f, cx1 = 0.f;

    // ---- load A tile for row-tile rt and refresh frags
    auto loadA = [&](int rt) {
        int row0 = rt * TTM;
#pragma unroll
        for (int q = 0; q < 2; q++) {
            int id = tid + q * THREADS, r = id >> 2, cc = id & 3;
            *(uint4*)(smem + S_AHI + r * PITCH + cc * 16) = *(const uint4*)(g_Fhi + (size_t)(row0 + r) * H_ + cc * 8);
            *(uint4*)(smem + S_ALO + r * PITCH + cc * 16) = *(const uint4*)(g_Flo + (size_t)(row0 + r) * H_ + cc * 8);
        }
        __syncthreads();
        ldmx4(aH0[0], aH0[1], aH0[2], aH0[3], sb + S_AHI + arow);
        ldmx4(aH1[0], aH1[1], aH1[2], aH1[3], sb + S_AHI + arow + 32);
        ldmx4(aL0[0], aL0[1], aL0[2], aL0[3], sb + S_ALO + arow);
        ldmx4(aL1[0], aL1[1], aL1[2], aL1[3], sb + S_ALO + arow + 32);
        cx0 = g_Fn[row0 + w * 16 + g];
        cx1 = g_Fn[row0 + w * 16 + g + 8];
    };

    // ---- preamble: A(rt of first item) + B/V/cy(tile of first item) into buf 0
    {
        int rt0 = s_c >> 6, t0 = s_c & 63;
        int mb = t0 * TTN;
        loadA(rt0);
        { int r = tid >> 2, cc = tid & 3;
          *(uint4*)(smem + S_B + r * PITCH + cc * 16)         = *(const uint4*)(g_Fhi + (size_t)(N_ + mb + r) * H_ + cc * 8);
          *(uint4*)(smem + S_B + 10240 + r * PITCH + cc * 16) = *(const uint4*)(g_Flo + (size_t)(N_ + mb + r) * H_ + cc * 8); }
        if (tid < 128)      *(uint4*)(smem + S_V + tid * 16)            = *(const uint4*)(g_Vhi + (size_t)(mb + tid) * T_);
        else if (tid < 256) *(uint4*)(smem + S_V + 2048 + (tid-128)*16) = *(const uint4*)(g_Vlo + (size_t)(mb + tid - 128) * T_);
        else if (tid < 384) ((float*)(smem + S_CY))[tid - 256] = g_Fn[N_ + mb + tid - 256];
        __syncthreads();
    }

    float oA0 = 0.f, oA1 = 0.f, oA2 = 0.f, oA3 = 0.f;
    float oB0 = 0.f, oB1 = 0.f, oB2 = 0.f, oB3 = 0.f;
    float s0 = 0.f, s1 = 0.f;
    int run = 0;
    int ib = 0;

#pragma unroll 1
    for (int ii = s_c; ii < e_c; ii++) {
        int rt = ii >> 6;
        bool pf = (ii + 1 < e_c);
        int ntile = (ii + 1) & 63;

        // prefetch next item's B/V/cy (tile-indexed, rt-independent)
        uint4 nbh, nbl, nv; float ncy = 0.f;
        if (pf) {
            int mb = ntile * TTN;
            { int r = tid >> 2, cc = tid & 3;
              nbh = *(const uint4*)(g_Fhi + (size_t)(N_ + mb + r) * H_ + cc * 8);
              nbl = *(const uint4*)(g_Flo + (size_t)(N_ + mb + r) * H_ + cc * 8); }
            if (tid < 128)      nv  = *(const uint4*)(g_Vhi + (size_t)(mb + tid) * T_);
            else if (tid < 256) nv  = *(const uint4*)(g_Vlo + (size_t)(mb + tid - 128) * T_);
            else if (tid < 384) ncy = g_Fn[N_ + mb + tid - 256];
        }

        u32 Bhi = sb + S_B + ib * 20480, Blo = Bhi + 10240;
        u32 Vhi = sb + S_V + ib * 4096,  Vlo = Vhi + 2048;
        const float* cyb = (const float*)(smem + S_CY + ib * 512);

#pragma unroll 1
        for (int s = 0; s < 8; s++) {
            u32 aP[4];
#pragma unroll
            for (int hhalf = 0; hhalf < 2; hhalf++) {
                int nc = 2 * s + hhalf;
                u32 bh[4], bl[4];
                ldmx4(bh[0], bh[1], bh[2], bh[3], Bhi + (u32)nc * (8 * PITCH) + bArow);
                ldmx4(bl[0], bl[1], bl[2], bl[3], Blo + (u32)nc * (8 * PITCH) + bArow);

                float cA0 = 0.f, cA1 = 0.f, cA2 = 0.f, cA3 = 0.f;
                float cB0 = 0.f, cB1 = 0.f, cB2 = 0.f, cB3 = 0.f;
                float cC0 = 0.f, cC1 = 0.f, cC2 = 0.f, cC3 = 0.f;
                mma16816(cA0, cA1, cA2, cA3, aH0[0], aH0[1], aH0[2], aH0[3], bh[0], bh[1]);
                mma16816(cB0, cB1, cB2, cB3, aH0[0], aH0[1], aH0[2], aH0[3], bl[0], bl[1]);
                mma16816(cC0, cC1, cC2, cC3, aL0[0], aL0[1], aL0[2], aL0[3], bh[0], bh[1]);
                mma16816(cA0, cA1, cA2, cA3, aH1[0], aH1[1], aH1[2], aH1[3], bh[2], bh[3]);
                mma16816(cB0, cB1, cB2, cB3, aH1[0], aH1[1], aH1[2], aH1[3], bl[2], bl[3]);
                mma16816(cC0, cC1, cC2, cC3, aL1[0], aL1[1], aL1[2], aL1[3], bh[2], bh[3]);
                float c0 = cA0 + cB0 + cC0, c1 = cA1 + cB1 + cC1;
                float c2 = cA2 + cB2 + cC2, c3 = cA3 + cB3 + cC3;

                float2 cy = *(const float2*)(cyb + nc * 8 + 2 * tig);
                float k0 = ex2f(fminf(c0 + (cx0 + cy.x), 0.f));
                float k1 = ex2f(fminf(c1 + (cx0 + cy.y), 0.f));
                float k2 = ex2f(fminf(c2 + (cx1 + cy.x), 0.f));
                float k3 = ex2f(fminf(c3 + (cx1 + cy.y), 0.f));

                u32 h01 = packh2(k0, k1), h23 = packh2(k2, k3);
                float2 f01 = __half22float2(*(__half2*)&h01);
                float2 f23 = __half22float2(*(__half2*)&h23);
                s0 += f01.x + f01.y;
                s1 += f23.x + f23.y;
                aP[2 * hhalf]     = h01;
                aP[2 * hhalf + 1] = h23;
            }

            u32 vh[2], vl[2];
            ldmx2t(vh[0], vh[1], Vhi + (u32)s * 256 + vArow);
            ldmx2t(vl[0], vl[1], Vlo + (u32)s * 256 + vArow);
            mma16816(oA0, oA1, oA2, oA3, aP[0], aP[1], aP[2], aP[3], vh[0], vh[1]);
            mma16816(oB0, oB1, oB2, oB3, aP[0], aP[1], aP[2], aP[3], vl[0], vl[1]);
        }

        // store prefetched tile
        if (pf) {
            int ib2 = ib ^ 1;
            { int r = tid >> 2, cc = tid & 3;
              *(uint4*)(smem + S_B + ib2 * 20480 + r * PITCH + cc * 16)         = nbh;
              *(uint4*)(smem + S_B + ib2 * 20480 + 10240 + r * PITCH + cc * 16) = nbl; }
            if (tid < 128)      *(uint4*)(smem + S_V + ib2 * 4096 + tid * 16)              = nv;
            else if (tid < 256) *(uint4*)(smem + S_V + ib2 * 4096 + 2048 + (tid-128) * 16) = nv;
            else if (tid < 384) ((float*)(smem + S_CY + ib2 * 512))[tid - 256] = ncy;
        }
        __syncthreads();
        ib ^= 1;

        // run boundary: flush partials; reload A if more items follow
        int nrt = pf ? ((ii + 1) >> 6) : -1;
        if (nrt != rt) {
            float o0 = oA0 + oB0, o1 = oA1 + oB1, o2 = oA2 + oB2, o3 = oA3 + oB3;
            float t0 = s0 + __shfl_xor_sync(0xffffffffu, s0, 1);
            t0 += __shfl_xor_sync(0xffffffffu, t0, 2);
            float t1 = s1 + __shfl_xor_sync(0xffffffffu, s1, 1);
            t1 += __shfl_xor_sync(0xffffffffu, t1, 2);
            int slot = c * 2 + run;
            int ra = w * 16 + g, rb = ra + 8;
            g_partR[IDXR(slot, 2 * tig,     ra)] = o0;
            g_partR[IDXR(slot, 2 * tig + 1, ra)] = o1;
            g_partR[IDXR(slot, 2 * tig,     rb)] = o2;
            g_partR[IDXR(slot, 2 * tig + 1, rb)] = o3;
            if (tig == 0) { g_partR[IDXR(slot, T_, ra)] = t0; g_partR[IDXR(slot, T_, rb)] = t1; }
            oA0 = oA1 = oA2 = oA3 = 0.f;
            oB0 = oB1 = oB2 = oB3 = 0.f;
            s0 = s1 = 0.f;
            run++;
            if (pf) loadA(nrt);
        }
    }
}

// ---------------- kernel 3: combine run partials, normalize ----------------
__global__ __launch_bounds__(256)
void reduce_kernel(float* __restrict__ out)
{
    int row = blockIdx.x * 256 + threadIdx.x;   // N_ rows
    int rt = row >> 8, rloc = row & 255;
    int fi = rt * 64;                            // first item of this row-tile
    float acc[T_ + 1];
#pragma unroll
    for (int t = 0; t <= T_; t++) acc[t] = 0.f;

    int c0 = (fi * NCTA) / NITEMS;
    int clo = c0 > 0 ? c0 - 1 : 0;
    int chi = c0 + 8 < NCTA ? c0 + 8 : NCTA;
#pragma unroll 1
    for (int cc = clo; cc < chi; cc++) {
        int s = item_lo(cc), e = item_lo(cc + 1);
        if (e <= fi || s >= fi + 64) continue;
        int runid = rt - (s >> 6);               // 0 or 1
        int slot = cc * 2 + runid;
#pragma unroll
        for (int t = 0; t <= T_; t++) acc[t] += g_partR[IDXR(slot, t, rloc)];
    }
    float inv = 1.f / acc[T_];
    float4* dst = (float4*)(out + (size_t)row * T_);
    dst[0] = make_float4(acc[0] * inv, acc[1] * inv, acc[2] * inv, acc[3] * inv);
    dst[1] = make_float4(acc[4] * inv, acc[5] * inv, acc[6] * inv, acc[7] * inv);
}

// ---------------- launch ----------------
extern "C" void kernel_launch(void* const* d_in, const int* in_sizes, int n_in,
                              void* d_out, int out_size)
{
    (void)in_sizes; (void)n_in; (void)out_size;
    const float* X  = (const float*)d_in[0];
    const float* Y  = (const float*)d_in[1];
    const float* Yt = (const float*)d_in[2];
    const float* W1 = (const float*)d_in[3];
    const float* b1 = (const float*)d_in[4];
    const float* W2 = (const float*)d_in[5];
    const float* b2 = (const float*)d_in[6];
    const float* W3 = (const float*)d_in[7];
    const float* b3 = (const float*)d_in[8];
    float* out = (float*)d_out;

    cudaFuncSetAttribute(mlp2_kernel, cudaFuncAttributeMaxDynamicSharedMemorySize, M2_TOTAL);
    cudaFuncSetAttribute(dist_kernel, cudaFuncAttributeMaxDynamicSharedMemorySize, SMEM_TOTAL);

    mlp2_kernel<<<MLP2BLKS + (M_ * T_) / 128, 128, M2_TOTAL>>>(X, Y, Yt, W1, b1, W2, b2, W3, b3);
    dist_kernel<<<NCTA, THREADS, SMEM_TOTAL>>>();
    reduce_kernel<<<N_ / 256, 256>>>(out);
}

// round 15
// speedup vs baseline: 1.2647x; 1.2647x over previous
#include <cuda_runtime.h>
#include <cuda_fp16.h>
#include <cstdint>

// Problem constants
#define N_  8192
#define M_  8192
#define D_  64
#define H_  32
#define T_  8

#define TTM    256                      // X rows per row-tile
#define TTN    128                      // Y rows per tile
#define NRT    (N_ / TTM)               // 32 row-tiles
#define NCHUNK (NRT * 32)               // 1024 chunks (2 Y-tiles each)
#define NCTA   148
#define THREADS 512
#define LOG2E     1.4426950408889634f
#define HALF_L2E  0.7213475204444817f

typedef unsigned long long u64;
typedef unsigned int u32;

// ---------------- global scratch ----------------
__device__ __half g_Fhi[(N_ + M_) * H_];   // X rows pre-scaled by log2e; Y rows raw
__device__ __half g_Flo[(N_ + M_) * H_];
__device__ float  g_Fn[N_ + M_];           // -0.5*log2e*||f||^2
__device__ __half g_Vhi[M_ * T_];          // Yt hi, [j][t]
__device__ __half g_Vlo[M_ * T_];
__device__ u32    g_ctr;                   // dynamic chunk counter (reset by mlp2)
// chunk partials: [chunk][t(0..8)][rloc(0..255)]  (slot = chunk id -> deterministic)
__device__ float  g_partC[NCHUNK * (T_ + 1) * TTM];
#define IDXC(c, t, rloc) (((((c) * (T_ + 1)) + (t)) << 8) + (rloc))

// ---------------- helpers ----------------
__device__ __forceinline__ u32 smem_u32(const void* p) {
    u32 a; asm("{ .reg .u64 t; cvta.to.shared.u64 t, %1; cvt.u32.u64 %0, t; }" : "=r"(a) : "l"(p));
    return a;
}
__device__ __forceinline__ float ex2f(float x) {
    float r; asm("ex2.approx.ftz.f32 %0, %1;" : "=f"(r) : "f"(x)); return r;
}
__device__ __forceinline__ void ldmx4(u32& r0, u32& r1, u32& r2, u32& r3, u32 addr) {
    asm volatile("ldmatrix.sync.aligned.m8n8.x4.shared.b16 {%0,%1,%2,%3}, [%4];"
        : "=r"(r0), "=r"(r1), "=r"(r2), "=r"(r3) : "r"(addr));
}
__device__ __forceinline__ void ldmx2t(u32& r0, u32& r1, u32 addr) {
    asm volatile("ldmatrix.sync.aligned.m8n8.x2.trans.shared.b16 {%0,%1}, [%2];"
        : "=r"(r0), "=r"(r1) : "r"(addr));
}
__device__ __forceinline__ void mma16816(float& c0, float& c1, float& c2, float& c3,
                                         u32 a0, u32 a1, u32 a2, u32 a3, u32 b0, u32 b1) {
    asm volatile("mma.sync.aligned.m16n8k16.row.col.f32.f16.f16.f32 "
        "{%0,%1,%2,%3},{%4,%5,%6,%7},{%8,%9},{%0,%1,%2,%3};"
        : "+f"(c0), "+f"(c1), "+f"(c2), "+f"(c3)
        : "r"(a0), "r"(a1), "r"(a2), "r"(a3), "r"(b0), "r"(b1));
}
__device__ __forceinline__ u32 packh2(float a, float b) {
    __half2 h = __floats2half2_rn(a, b);
    return *(u32*)&h;
}

// ---------------- dist SMEM layout ----------------
#define PITCH   80
#define S_AHI   0                       // 256 rows * 80B
#define S_ALO   20480
#define S_B     40960                   // [stage][hi/lo]
#define S_V     81920                   // [stage][hi/lo]
#define S_CY    90112                   // [stage] 512B each, 2 stages -> ends 91136
#define S_NXT   91136                   // chunk-id broadcast word (16B slot)
#define SMEM_TOTAL 91152

// ---------------- mlp2 SMEM layout (128 rows/CTA, as R11) ----------------
#define XP      144
#define M2_FH   0
#define M2_FL   18432
#define M2_WH   36864
#define M2_WL   47104
#define M2_BI   57344
#define M2_TOTAL 57728

// ---------------- kernel 1: MLP on tensor cores + fused V prep + ctr reset ----------------
#define MLP2BLKS ((N_ + M_) / 128)      // 128
__global__ __launch_bounds__(256)
void mlp2_kernel(const float* __restrict__ X, const float* __restrict__ Y,
                 const float* __restrict__ Yt,
                 const float* __restrict__ W1, const float* __restrict__ b1,
                 const float* __restrict__ W2, const float* __restrict__ b2,
                 const float* __restrict__ W3, const float* __restrict__ b3)
{
    if (blockIdx.x >= MLP2BLKS) {           // tail blocks: build V hi/lo
        int bx = blockIdx.x - MLP2BLKS;
        if (bx == 0 && threadIdx.x == 0) g_ctr = 0;     // reset chunk counter
        int idx = bx * 256 + threadIdx.x;   // M_*T_
        float v = Yt[idx];
        __half hi = __float2half_rn(v);
        g_Vhi[idx] = hi;
        g_Vlo[idx] = __float2half_rn(v - __half2float(hi));
        return;
    }

    extern __shared__ char smem[];
    u32 sb = smem_u32(smem);
    int tid = threadIdx.x, w = tid >> 5, l = tid & 31;
    int g = l >> 2, tig = l & 3;
    int row0 = blockIdx.x * 128;
    bool isX = (row0 < N_);
    const float* src = isX ? (X + (size_t)row0 * D_) : (Y + (size_t)(row0 - N_) * D_);

#pragma unroll
    for (int q = 0; q < 8; q++) {
        int idx = q * 256 + tid;
        int r = idx >> 4, c4 = idx & 15;
        float4 v = ((const float4*)src)[idx];
        float hx = __half2float(__float2half_rn(v.x));
        float hy = __half2float(__float2half_rn(v.y));
        float hz = __half2float(__float2half_rn(v.z));
        float hw = __half2float(__float2half_rn(v.w));
        u32* ph = (u32*)(smem + M2_FH + r * XP + c4 * 8);
        u32* pl = (u32*)(smem + M2_FL + r * XP + c4 * 8);
        ph[0] = packh2(v.x, v.y);        ph[1] = packh2(v.z, v.w);
        pl[0] = packh2(v.x - hx, v.y - hy); pl[1] = packh2(v.z - hz, v.w - hw);
    }
#pragma unroll
    for (int q = 0; q < 2; q++) {
        int idx = q * 256 + tid;
        int r = idx >> 3, c4 = idx & 7;
        float4 v = ((const float4*)W1)[idx];
        float hx = __half2float(__float2half_rn(v.x));
        float hy = __half2float(__float2half_rn(v.y));
        float hz = __half2float(__float2half_rn(v.z));
        float hw = __half2float(__float2half_rn(v.w));
        u32* ph = (u32*)(smem + M2_WH + r * PITCH + c4 * 8);
        u32* pl = (u32*)(smem + M2_WL + r * PITCH + c4 * 8);
        ph[0] = packh2(v.x, v.y);        ph[1] = packh2(v.z, v.w);
        pl[0] = packh2(v.x - hx, v.y - hy); pl[1] = packh2(v.z - hz, v.w - hw);
    }
    {
        const float4* Wsrc[2] = { (const float4*)W2, (const float4*)W3 };
#pragma unroll
        for (int m = 0; m < 2; m++) {
            int r = 64 + m * 32 + (tid >> 3), c4 = tid & 7;
            float4 v = Wsrc[m][tid];
            float hx = __half2float(__float2half_rn(v.x));
            float hy = __half2float(__float2half_rn(v.y));
            float hz = __half2float(__float2half_rn(v.z));
            float hw = __half2float(__float2half_rn(v.w));
            u32* ph = (u32*)(smem + M2_WH + r * PITCH + c4 * 8);
            u32* pl = (u32*)(smem + M2_WL + r * PITCH + c4 * 8);
            ph[0] = packh2(v.x, v.y);        ph[1] = packh2(v.z, v.w);
            pl[0] = packh2(v.x - hx, v.y - hy); pl[1] = packh2(v.z - hz, v.w - hw);
        }
    }
    if (tid < 96) {
        float bv = (tid < 32) ? b1[tid] : (tid < 64) ? b2[tid - 32] : b3[tid - 64];
        ((float*)(smem + M2_BI))[tid] = bv;
    }
    __syncthreads();

    const float* sbias = (const float*)(smem + M2_BI);

    u32 aH[4][4], aL[4][4];
    {
        u32 arow = (u32)(w * 16 + (l & 15)) * XP + (u32)(l >> 4) * 16;
#pragma unroll
        for (int ks = 0; ks < 4; ks++) {
            ldmx4(aH[ks][0], aH[ks][1], aH[ks][2], aH[ks][3], sb + M2_FH + arow + ks * 32);
            ldmx4(aL[ks][0], aL[ks][1], aL[ks][2], aL[ks][3], sb + M2_FL + arow + ks * 32);
        }
    }
    u32 brow = (u32)(l & 15) * PITCH;

    u32 h1H[2][4], h1L[2][4];
#pragma unroll
    for (int nc = 0; nc < 4; nc++) {
        float cA[4] = {0,0,0,0}, cB[4] = {0,0,0,0}, cC[4] = {0,0,0,0};
#pragma unroll
        for (int ks = 0; ks < 4; ks++) {
            u32 woff = (u32)(ks * 16) * PITCH + (u32)nc * 16 + brow;
            u32 wh0, wh1, wl0, wl1;
            ldmx2t(wh0, wh1, sb + M2_WH + woff);
            ldmx2t(wl0, wl1, sb + M2_WL + woff);
            mma16816(cA[0],cA[1],cA[2],cA[3], aH[ks][0],aH[ks][1],aH[ks][2],aH[ks][3], wh0, wh1);
            mma16816(cB[0],cB[1],cB[2],cB[3], aH[ks][0],aH[ks][1],aH[ks][2],aH[ks][3], wl0, wl1);
            mma16816(cC[0],cC[1],cC[2],cC[3], aL[ks][0],aL[ks][1],aL[ks][2],aL[ks][3], wh0, wh1);
        }
        float b0 = sbias[nc * 8 + 2 * tig], b1v = sbias[nc * 8 + 2 * tig + 1];
        float v0 = fmaxf(cA[0] + cB[0] + cC[0] + b0,  0.f);
        float v1 = fmaxf(cA[1] + cB[1] + cC[1] + b1v, 0.f);
        float v2 = fmaxf(cA[2] + cB[2] + cC[2] + b0,  0.f);
        float v3 = fmaxf(cA[3] + cB[3] + cC[3] + b1v, 0.f);
        u32 h01 = packh2(v0, v1), h23 = packh2(v2, v3);
        float2 f01 = __half22float2(*(__half2*)&h01), f23 = __half22float2(*(__half2*)&h23);
        int ks2 = nc >> 1, pos = (nc & 1) * 2;
        h1H[ks2][pos] = h01; h1H[ks2][pos + 1] = h23;
        h1L[ks2][pos]     = packh2(v0 - f01.x, v1 - f01.y);
        h1L[ks2][pos + 1] = packh2(v2 - f23.x, v3 - f23.y);
    }

    u32 h2H[2][4], h2L[2][4];
#pragma unroll
    for (int nc = 0; nc < 4; nc++) {
        float cA[4] = {0,0,0,0}, cB[4] = {0,0,0,0}, cC[4] = {0,0,0,0};
#pragma unroll
        for (int ks = 0; ks < 2; ks++) {
            u32 woff = (u32)(64 + ks * 16) * PITCH + (u32)nc * 16 + brow;
            u32 wh0, wh1, wl0, wl1;
            ldmx2t(wh0, wh1, sb + M2_WH + woff);
            ldmx2t(wl0, wl1, sb + M2_WL + woff);
            mma16816(cA[0],cA[1],cA[2],cA[3], h1H[ks][0],h1H[ks][1],h1H[ks][2],h1H[ks][3], wh0, wh1);
            mma16816(cB[0],cB[1],cB[2],cB[3], h1H[ks][0],h1H[ks][1],h1H[ks][2],h1H[ks][3], wl0, wl1);
            mma16816(cC[0],cC[1],cC[2],cC[3], h1L[ks][0],h1L[ks][1],h1L[ks][2],h1L[ks][3], wh0, wh1);
        }
        float b0 = sbias[32 + nc * 8 + 2 * tig], b1v = sbias[32 + nc * 8 + 2 * tig + 1];
        float v0 = fmaxf(cA[0] + cB[0] + cC[0] + b0,  0.f);
        float v1 = fmaxf(cA[1] + cB[1] + cC[1] + b1v, 0.f);
        float v2 = fmaxf(cA[2] + cB[2] + cC[2] + b0,  0.f);
        float v3 = fmaxf(cA[3] + cB[3] + cC[3] + b1v, 0.f);
        u32 h01 = packh2(v0, v1), h23 = packh2(v2, v3);
        float2 f01 = __half22float2(*(__half2*)&h01), f23 = __half22float2(*(__half2*)&h23);
        int ks2 = nc >> 1, pos = (nc & 1) * 2;
        h2H[ks2][pos] = h01; h2H[ks2][pos + 1] = h23;
        h2L[ks2][pos]     = packh2(v0 - f01.x, v1 - f01.y);
        h2L[ks2][pos + 1] = packh2(v2 - f23.x, v3 - f23.y);
    }

    float nxA = 0.f, nxB = 0.f;
    int rg = row0 + w * 16 + g;
    float sc = isX ? LOG2E : 1.f;
#pragma unroll
    for (int nc = 0; nc < 4; nc++) {
        float cA[4] = {0,0,0,0}, cB[4] = {0,0,0,0}, cC[4] = {0,0,0,0};
#pragma unroll
        for (int ks = 0; ks < 2; ks++) {
            u32 woff = (u32)(96 + ks * 16) * PITCH + (u32)nc * 16 + brow;
            u32 wh0, wh1, wl0, wl1;
            ldmx2t(wh0, wh1, sb + M2_WH + woff);
            ldmx2t(wl0, wl1, sb + M2_WL + woff);
            mma16816(cA[0],cA[1],cA[2],cA[3], h2H[ks][0],h2H[ks][1],h2H[ks][2],h2H[ks][3], wh0, wh1);
            mma16816(cB[0],cB[1],cB[2],cB[3], h2H[ks][0],h2H[ks][1],h2H[ks][2],h2H[ks][3], wl0, wl1);
            mma16816(cC[0],cC[1],cC[2],cC[3], h2L[ks][0],h2L[ks][1],h2L[ks][2],h2L[ks][3], wh0, wh1);
        }
        float b0 = sbias[64 + nc * 8 + 2 * tig], b1v = sbias[64 + nc * 8 + 2 * tig + 1];
        float v0 = fmaxf(cA[0] + cB[0] + cC[0] + b0,  0.f);
        float v1 = fmaxf(cA[1] + cB[1] + cC[1] + b1v, 0.f);
        float v2 = fmaxf(cA[2] + cB[2] + cC[2] + b0,  0.f);
        float v3 = fmaxf(cA[3] + cB[3] + cC[3] + b1v, 0.f);
        nxA += v0 * v0 + v1 * v1;
        nxB += v2 * v2 + v3 * v3;
        float s0 = v0 * sc, s1 = v1 * sc, s2 = v2 * sc, s3 = v3 * sc;
        u32 h01 = packh2(s0, s1), h23 = packh2(s2, s3);
        float2 f01 = __half22float2(*(__half2*)&h01), f23 = __half22float2(*(__half2*)&h23);
        u32 l01 = packh2(s0 - f01.x, s1 - f01.y), l23 = packh2(s2 - f23.x, s3 - f23.y);
        ((u32*)g_Fhi)[rg * 16 + nc * 4 + tig]       = h01;
        ((u32*)g_Fhi)[(rg + 8) * 16 + nc * 4 + tig] = h23;
        ((u32*)g_Flo)[rg * 16 + nc * 4 + tig]       = l01;
        ((u32*)g_Flo)[(rg + 8) * 16 + nc * 4 + tig] = l23;
    }
    nxA += __shfl_xor_sync(0xffffffffu, nxA, 1);
    nxA += __shfl_xor_sync(0xffffffffu, nxA, 2);
    nxB += __shfl_xor_sync(0xffffffffu, nxB, 1);
    nxB += __shfl_xor_sync(0xffffffffu, nxB, 2);
    if (tig == 0) {
        g_Fn[rg]     = -HALF_L2E * nxA;
        g_Fn[rg + 8] = -HALF_L2E * nxB;
    }
}

// ---------------- kernel 2: persistent dynamic-chunk HMMA flash kernel ----------------
// A frags are named scalars (cannot spill to indexed local memory).

#define LOAD_A(RT) do {                                                                              \
    int row0_ = (RT) * TTM;                                                                          \
    _Pragma("unroll")                                                                                \
    for (int q_ = 0; q_ < 2; q_++) {                                                                 \
        int id_ = tid + q_ * THREADS, r_ = id_ >> 2, cc_ = id_ & 3;                                  \
        *(uint4*)(smem + S_AHI + r_ * PITCH + cc_ * 16) = *(const uint4*)(g_Fhi + (size_t)(row0_ + r_) * H_ + cc_ * 8); \
        *(uint4*)(smem + S_ALO + r_ * PITCH + cc_ * 16) = *(const uint4*)(g_Flo + (size_t)(row0_ + r_) * H_ + cc_ * 8); \
    }                                                                                                \
    __syncthreads();                                                                                 \
    ldmx4(h00, h01, h02, h03, sb + S_AHI + arow);                                                    \
    ldmx4(h10, h11, h12, h13, sb + S_AHI + arow + 32);                                               \
    ldmx4(l00, l01, l02, l03, sb + S_ALO + arow);                                                    \
    ldmx4(l10, l11, l12, l13, sb + S_ALO + arow + 32);                                               \
    cx0 = g_Fn[row0_ + w * 16 + g];                                                                  \
    cx1 = g_Fn[row0_ + w * 16 + g + 8];                                                              \
} while (0)

#define PROCESS(IB, PFT) do {                                                                        \
    uint4 nbh_, nbl_, nv_; float ncy_ = 0.f; int pft_ = (PFT);                                       \
    if (pft_ >= 0) {                                                                                 \
        int mb_ = pft_ * TTN;                                                                        \
        { int r_ = tid >> 2, cc_ = tid & 3;                                                          \
          nbh_ = *(const uint4*)(g_Fhi + (size_t)(N_ + mb_ + r_) * H_ + cc_ * 8);                    \
          nbl_ = *(const uint4*)(g_Flo + (size_t)(N_ + mb_ + r_) * H_ + cc_ * 8); }                  \
        if (tid < 128)      nv_  = *(const uint4*)(g_Vhi + (size_t)(mb_ + tid) * T_);                \
        else if (tid < 256) nv_  = *(const uint4*)(g_Vlo + (size_t)(mb_ + tid - 128) * T_);          \
        else if (tid < 384) ncy_ = g_Fn[N_ + mb_ + tid - 256];                                       \
    }                                                                                                \
    u32 Bhi_ = sb + S_B + (IB) * 20480, Blo_ = Bhi_ + 10240;                                         \
    u32 Vhi_ = sb + S_V + (IB) * 4096,  Vlo_ = Vhi_ + 2048;                                          \
    const float* cyb_ = (const float*)(smem + S_CY + (IB) * 512);                                    \
    _Pragma("unroll 1")                                                                              \
    for (int s_ = 0; s_ < 8; s_++) {                                                                 \
        u32 aP0_, aP1_, aP2_, aP3_;                                                                  \
        _Pragma("unroll")                                                                            \
        for (int hh_ = 0; hh_ < 2; hh_++) {                                                          \
            int nc_ = 2 * s_ + hh_;                                                                  \
            u32 bh0_, bh1_, bh2_, bh3_, bl0_, bl1_, bl2_, bl3_;                                      \
            ldmx4(bh0_, bh1_, bh2_, bh3_, Bhi_ + (u32)nc_ * (8 * PITCH) + bArow);                    \
            ldmx4(bl0_, bl1_, bl2_, bl3_, Blo_ + (u32)nc_ * (8 * PITCH) + bArow);                    \
            float cA0_=0.f,cA1_=0.f,cA2_=0.f,cA3_=0.f;                                               \
            float cB0_=0.f,cB1_=0.f,cB2_=0.f,cB3_=0.f;                                               \
            float cC0_=0.f,cC1_=0.f,cC2_=0.f,cC3_=0.f;                                               \
            mma16816(cA0_,cA1_,cA2_,cA3_, h00,h01,h02,h03, bh0_, bh1_);                              \
            mma16816(cB0_,cB1_,cB2_,cB3_, h00,h01,h02,h03, bl0_, bl1_);                              \
            mma16816(cC0_,cC1_,cC2_,cC3_, l00,l01,l02,l03, bh0_, bh1_);                              \
            mma16816(cA0_,cA1_,cA2_,cA3_, h10,h11,h12,h13, bh2_, bh3_);                              \
            mma16816(cB0_,cB1_,cB2_,cB3_, h10,h11,h12,h13, bl2_, bl3_);                              \
            mma16816(cC0_,cC1_,cC2_,cC3_, l10,l11,l12,l13, bh2_, bh3_);                              \
            float c0_ = cA0_+cB0_+cC0_, c1_ = cA1_+cB1_+cC1_;                                        \
            float c2_ = cA2_+cB2_+cC2_, c3_ = cA3_+cB3_+cC3_;                                        \
            float2 cy_ = *(const float2*)(cyb_ + nc_ * 8 + 2 * tig);                                 \
            float k0_ = ex2f(fminf(c0_ + (cx0 + cy_.x), 0.f));                                       \
            float k1_ = ex2f(fminf(c1_ + (cx0 + cy_.y), 0.f));                                       \
            float k2_ = ex2f(fminf(c2_ + (cx1 + cy_.x), 0.f));                                       \
            float k3_ = ex2f(fminf(c3_ + (cx1 + cy_.y), 0.f));                                       \
            u32 h01_ = packh2(k0_, k1_), h23_ = packh2(k2_, k3_);                                    \
            float2 f01_ = __half22float2(*(__half2*)&h01_);                                          \
            float2 f23_ = __half22float2(*(__half2*)&h23_);                                          \
            s0 += f01_.x + f01_.y;                                                                   \
            s1 += f23_.x + f23_.y;                                                                   \
            if (hh_ == 0) { aP0_ = h01_; aP1_ = h23_; } else { aP2_ = h01_; aP3_ = h23_; }           \
        }                                                                                            \
        u32 vh0_, vh1_, vl0_, vl1_;                                                                  \
        ldmx2t(vh0_, vh1_, Vhi_ + (u32)s_ * 256 + vArow);                                            \
        ldmx2t(vl0_, vl1_, Vlo_ + (u32)s_ * 256 + vArow);                                            \
        mma16816(oA0, oA1, oA2, oA3, aP0_, aP1_, aP2_, aP3_, vh0_, vh1_);                            \
        mma16816(oB0, oB1, oB2, oB3, aP0_, aP1_, aP2_, aP3_, vl0_, vl1_);                            \
    }                                                                                                \
    if (pft_ >= 0) {                                                                                 \
        int ib2_ = (IB) ^ 1;                                                                         \
        { int r_ = tid >> 2, cc_ = tid & 3;                                                          \
          *(uint4*)(smem + S_B + ib2_ * 20480 + r_ * PITCH + cc_ * 16)         = nbh_;               \
          *(uint4*)(smem + S_B + ib2_ * 20480 + 10240 + r_ * PITCH + cc_ * 16) = nbl_; }             \
        if (tid < 128)      *(uint4*)(smem + S_V + ib2_ * 4096 + tid * 16)              = nv_;       \
        else if (tid < 256) *(uint4*)(smem + S_V + ib2_ * 4096 + 2048 + (tid-128) * 16) = nv_;       \
        else if (tid < 384) ((float*)(smem + S_CY + ib2_ * 512))[tid - 256] = ncy_;                  \
    }                                                                                                \
    __syncthreads();                                                                                 \
} while (0)

#define FLUSH(C) do {                                                                                \
    float o0_ = oA0 + oB0, o1_ = oA1 + oB1, o2_ = oA2 + oB2, o3_ = oA3 + oB3;                        \
    float t0_ = s0 + __shfl_xor_sync(0xffffffffu, s0, 1); t0_ += __shfl_xor_sync(0xffffffffu, t0_, 2); \
    float t1_ = s1 + __shfl_xor_sync(0xffffffffu, s1, 1); t1_ += __shfl_xor_sync(0xffffffffu, t1_, 2); \
    int ra_ = w * 16 + g, rb_ = ra_ + 8;                                                             \
    g_partC[IDXC((C), 2 * tig,     ra_)] = o0_;                                                      \
    g_partC[IDXC((C), 2 * tig + 1, ra_)] = o1_;                                                      \
    g_partC[IDXC((C), 2 * tig,     rb_)] = o2_;                                                      \
    g_partC[IDXC((C), 2 * tig + 1, rb_)] = o3_;                                                      \
    if (tig == 0) { g_partC[IDXC((C), T_, ra_)] = t0_; g_partC[IDXC((C), T_, rb_)] = t1_; }          \
    oA0 = oA1 = oA2 = oA3 = 0.f; oB0 = oB1 = oB2 = oB3 = 0.f; s0 = s1 = 0.f;                         \
} while (0)

__global__ __launch_bounds__(THREADS)
void dist_kernel()
{
    extern __shared__ char smem[];
    u32 sb = smem_u32(smem);
    int tid = threadIdx.x, w = tid >> 5, l = tid & 31;
    int g = l >> 2, tig = l & 3;

    u32 bArow = (u32)(l & 7) * PITCH + (u32)(l >> 3) * 16;
    u32 vArow = (u32)(l & 15) * 16;
    u32 arow  = (u32)(w * 16 + (l & 15)) * PITCH + (u32)(l >> 4) * 16;

    u32* nxt_slot = (u32*)(smem + S_NXT);

    // A fragments as named scalars + cx
    u32 h00, h01, h02, h03, h10, h11, h12, h13;
    u32 l00, l01, l02, l03, l10, l11, l12, l13;
    float cx0, cx1;

    // accumulators
    float oA0 = 0.f, oA1 = 0.f, oA2 = 0.f, oA3 = 0.f;
    float oB0 = 0.f, oB1 = 0.f, oB2 = 0.f, oB3 = 0.f;
    float s0 = 0.f, s1 = 0.f;

    // first chunk (always valid: NCHUNK > NCTA)
    int cur;
    if (tid == 0) nxt_slot[0] = atomicAdd(&g_ctr, 1);
    __syncthreads();
    cur = nxt_slot[0];
    __syncthreads();
    int currt = cur >> 5;
    LOAD_A(currt);
    {   // preamble: B/V/cy of cur's first tile into buf0
        int mb = ((2 * cur) & 63) * TTN;
        { int r = tid >> 2, cc = tid & 3;
          *(uint4*)(smem + S_B + r * PITCH + cc * 16)         = *(const uint4*)(g_Fhi + (size_t)(N_ + mb + r) * H_ + cc * 8);
          *(uint4*)(smem + S_B + 10240 + r * PITCH + cc * 16) = *(const uint4*)(g_Flo + (size_t)(N_ + mb + r) * H_ + cc * 8); }
        if (tid < 128)      *(uint4*)(smem + S_V + tid * 16)            = *(const uint4*)(g_Vhi + (size_t)(mb + tid) * T_);
        else if (tid < 256) *(uint4*)(smem + S_V + 2048 + (tid-128)*16) = *(const uint4*)(g_Vlo + (size_t)(mb + tid - 128) * T_);
        else if (tid < 384) ((float*)(smem + S_CY))[tid - 256] = g_Fn[N_ + mb + tid - 256];
        __syncthreads();
    }

    int ib = 0;
#pragma unroll 1
    while (true) {
        // grab next chunk early (uniform broadcast through smem)
        if (tid == 0) nxt_slot[0] = atomicAdd(&g_ctr, 1);
        // tile 0 of cur; prefetch tile 1 of cur
        PROCESS(ib, (2 * cur + 1) & 63);
        ib ^= 1;
        int nxt = nxt_slot[0];                  // valid: PROCESS ended with __syncthreads
        // tile 1 of cur; prefetch nxt's tile 0 if valid
        PROCESS(ib, (nxt < NCHUNK ? ((2 * nxt) & 63) : -1));
        ib ^= 1;
        FLUSH(cur);
        if (nxt >= NCHUNK) break;
        int nrt = nxt >> 5;
        if (nrt != currt) { LOAD_A(nrt); currt = nrt; }
        cur = nxt;
    }
}

// ---------------- kernel 3: combine chunk partials, normalize ----------------
__global__ __launch_bounds__(256)
void reduce_kernel(float* __restrict__ out)
{
    int row = blockIdx.x * 256 + threadIdx.x;   // N_ rows; block = one row-tile
    int rt = row >> 8, rloc = row & 255;
    float acc[T_ + 1];
#pragma unroll
    for (int t = 0; t <= T_; t++) acc[t] = 0.f;
#pragma unroll 1
    for (int k = 0; k < 32; k++) {
        int c = rt * 32 + k;
#pragma unroll
        for (int t = 0; t <= T_; t++) acc[t] += g_partC[IDXC(c, t, rloc)];
    }
    float inv = 1.f / acc[T_];
    float4* dst = (float4*)(out + (size_t)row * T_);
    dst[0] = make_float4(acc[0] * inv, acc[1] * inv, acc[2] * inv, acc[3] * inv);
    dst[1] = make_float4(acc[4] * inv, acc[5] * inv, acc[6] * inv, acc[7] * inv);
}

// ---------------- launch ----------------
extern "C" void kernel_launch(void* const* d_in, const int* in_sizes, int n_in,
                              void* d_out, int out_size)
{
    (void)in_sizes; (void)n_in; (void)out_size;
    const float* X  = (const float*)d_in[0];
    const float* Y  = (const float*)d_in[1];
    const float* Yt = (const float*)d_in[2];
    const float* W1 = (const float*)d_in[3];
    const float* b1 = (const float*)d_in[4];
    const float* W2 = (const float*)d_in[5];
    const float* b2 = (const float*)d_in[6];
    const float* W3 = (const float*)d_in[7];
    const float* b3 = (const float*)d_in[8];
    float* out = (float*)d_out;

    cudaFuncSetAttribute(mlp2_kernel, cudaFuncAttributeMaxDynamicSharedMemorySize, M2_TOTAL);
    cudaFuncSetAttribute(dist_kernel, cudaFuncAttributeMaxDynamicSharedMemorySize, SMEM_TOTAL);

    mlp2_kernel<<<MLP2BLKS + (M_ * T_) / 256, 256, M2_TOTAL>>>(X, Y, Yt, W1, b1, W2, b2, W3, b3);
    dist_kernel<<<NCTA, THREADS, SMEM_TOTAL>>>();
    reduce_kernel<<<N_ / 256, 256>>>(out);
}

// round 16
// speedup vs baseline: 1.4942x; 1.1815x over previous
#include <cuda_runtime.h>
#include <cuda_fp16.h>
#include <cstdint>

// Problem constants
#define N_  8192
#define M_  8192
#define D_  64
#define H_  32
#define T_  8

#define MSPLIT 4
#define TTM    256                      // X rows per CTA (dist)
#define TTN    128                      // Y rows per tile iter
#define TILES  ((M_ / MSPLIT) / TTN)    // 16
#define THREADS 512
#define LOG2E     1.4426950408889634f
#define HALF_L2E  0.7213475204444817f

typedef unsigned long long u64;
typedef unsigned int u32;

// ---------------- global scratch ----------------
__device__ __half g_Fhi[(N_ + M_) * H_];   // X rows pre-scaled by log2e; Y rows raw
__device__ __half g_Flo[(N_ + M_) * H_];
__device__ float  g_Fn[N_ + M_];           // -0.5*log2e*||f||^2
__device__ __half g_Vhi[M_ * T_];          // Yt hi, [j][t]
__device__ __half g_Vlo[M_ * T_];
// partials transposed for coalesced reduce: [chunk][t(0..8)][row]
__device__ float  g_part[MSPLIT * (T_ + 1) * N_];
#define IDXP(c, t, row) ((((c) * (T_ + 1)) + (t)) * N_ + (row))

// ---------------- helpers ----------------
__device__ __forceinline__ u32 smem_u32(const void* p) {
    u32 a; asm("{ .reg .u64 t; cvta.to.shared.u64 t, %1; cvt.u32.u64 %0, t; }" : "=r"(a) : "l"(p));
    return a;
}
__device__ __forceinline__ float ex2f(float x) {
    float r; asm("ex2.approx.ftz.f32 %0, %1;" : "=f"(r) : "f"(x)); return r;
}
__device__ __forceinline__ void ldmx4(u32& r0, u32& r1, u32& r2, u32& r3, u32 addr) {
    asm volatile("ldmatrix.sync.aligned.m8n8.x4.shared.b16 {%0,%1,%2,%3}, [%4];"
        : "=r"(r0), "=r"(r1), "=r"(r2), "=r"(r3) : "r"(addr));
}
__device__ __forceinline__ void ldmx2t(u32& r0, u32& r1, u32 addr) {
    asm volatile("ldmatrix.sync.aligned.m8n8.x2.trans.shared.b16 {%0,%1}, [%2];"
        : "=r"(r0), "=r"(r1) : "r"(addr));
}
__device__ __forceinline__ void mma16816(float& c0, float& c1, float& c2, float& c3,
                                         u32 a0, u32 a1, u32 a2, u32 a3, u32 b0, u32 b1) {
    asm volatile("mma.sync.aligned.m16n8k16.row.col.f32.f16.f16.f32 "
        "{%0,%1,%2,%3},{%4,%5,%6,%7},{%8,%9},{%0,%1,%2,%3};"
        : "+f"(c0), "+f"(c1), "+f"(c2), "+f"(c3)
        : "r"(a0), "r"(a1), "r"(a2), "r"(a3), "r"(b0), "r"(b1));
}
__device__ __forceinline__ u32 packh2(float a, float b) {
    __half2 h = __floats2half2_rn(a, b);
    return *(u32*)&h;
}

// ---------------- dist SMEM layout ----------------
#define PITCH   80                      // 64B data + 16B pad -> conflict-free ldmatrix
#define S_AHI   0                       // 256 rows * 80B
#define S_ALO   20480
#define S_B     40960                   // [stage][hi/lo]: stage*20480, lo +10240
#define S_V     81920                   // [stage][hi/lo]: stage*4096, lo +2048
#define S_CY    90112                   // [stage] 512B, 2 stages
#define S_VONE  91136                   // constant ones block (rows x [1,0,..,0]), 512B
#define SMEM_TOTAL 91648

// ---------------- mlp2 SMEM layout (dynamic) ----------------
#define XP      144                     // X row pitch bytes (128B data + 16 pad)
#define M2_FH   0                       // 128*144 = 18432
#define M2_FL   18432
#define M2_WH   36864                   // 128 rows (W1:0-63, W2:64-95, W3:96-127) * 80B
#define M2_WL   47104
#define M2_BI   57344                   // 96 floats
#define M2_TOTAL 57728

// ---------------- kernel 1: MLP on tensor cores + fused V prep ----------------
#define MLP2BLKS ((N_ + M_) / 128)      // 128
__global__ __launch_bounds__(256)
void mlp2_kernel(const float* __restrict__ X, const float* __restrict__ Y,
                 const float* __restrict__ Yt,
                 const float* __restrict__ W1, const float* __restrict__ b1,
                 const float* __restrict__ W2, const float* __restrict__ b2,
                 const float* __restrict__ W3, const float* __restrict__ b3)
{
    if (blockIdx.x >= MLP2BLKS) {           // tail blocks: build V hi/lo
        int idx = (blockIdx.x - MLP2BLKS) * 256 + threadIdx.x;  // M_*T_
        float v = Yt[idx];
        __half hi = __float2half_rn(v);
        g_Vhi[idx] = hi;
        g_Vlo[idx] = __float2half_rn(v - __half2float(hi));
        return;
    }

    extern __shared__ char smem[];
    u32 sb = smem_u32(smem);
    int tid = threadIdx.x, w = tid >> 5, l = tid & 31;
    int g = l >> 2, tig = l & 3;
    int row0 = blockIdx.x * 128;
    bool isX = (row0 < N_);
    const float* src = isX ? (X + (size_t)row0 * D_) : (Y + (size_t)(row0 - N_) * D_);

#pragma unroll
    for (int q = 0; q < 8; q++) {
        int idx = q * 256 + tid;
        int r = idx >> 4, c4 = idx & 15;
        float4 v = ((const float4*)src)[idx];
        float hx = __half2float(__float2half_rn(v.x));
        float hy = __half2float(__float2half_rn(v.y));
        float hz = __half2float(__float2half_rn(v.z));
        float hw = __half2float(__float2half_rn(v.w));
        u32* ph = (u32*)(smem + M2_FH + r * XP + c4 * 8);
        u32* pl = (u32*)(smem + M2_FL + r * XP + c4 * 8);
        ph[0] = packh2(v.x, v.y);        ph[1] = packh2(v.z, v.w);
        pl[0] = packh2(v.x - hx, v.y - hy); pl[1] = packh2(v.z - hz, v.w - hw);
    }
#pragma unroll
    for (int q = 0; q < 2; q++) {
        int idx = q * 256 + tid;
        int r = idx >> 3, c4 = idx & 7;
        float4 v = ((const float4*)W1)[idx];
        float hx = __half2float(__float2half_rn(v.x));
        float hy = __half2float(__float2half_rn(v.y));
        float hz = __half2float(__float2half_rn(v.z));
        float hw = __half2float(__float2half_rn(v.w));
        u32* ph = (u32*)(smem + M2_WH + r * PITCH + c4 * 8);
        u32* pl = (u32*)(smem + M2_WL + r * PITCH + c4 * 8);
        ph[0] = packh2(v.x, v.y);        ph[1] = packh2(v.z, v.w);
        pl[0] = packh2(v.x - hx, v.y - hy); pl[1] = packh2(v.z - hz, v.w - hw);
    }
    {
        const float4* Wsrc[2] = { (const float4*)W2, (const float4*)W3 };
#pragma unroll
        for (int m = 0; m < 2; m++) {
            int r = 64 + m * 32 + (tid >> 3), c4 = tid & 7;
            float4 v = Wsrc[m][tid];
            float hx = __half2float(__float2half_rn(v.x));
            float hy = __half2float(__float2half_rn(v.y));
            float hz = __half2float(__float2half_rn(v.z));
            float hw = __half2float(__float2half_rn(v.w));
            u32* ph = (u32*)(smem + M2_WH + r * PITCH + c4 * 8);
            u32* pl = (u32*)(smem + M2_WL + r * PITCH + c4 * 8);
            ph[0] = packh2(v.x, v.y);        ph[1] = packh2(v.z, v.w);
            pl[0] = packh2(v.x - hx, v.y - hy); pl[1] = packh2(v.z - hz, v.w - hw);
        }
    }
    if (tid < 96) {
        float bv = (tid < 32) ? b1[tid] : (tid < 64) ? b2[tid - 32] : b3[tid - 64];
        ((float*)(smem + M2_BI))[tid] = bv;
    }
    __syncthreads();

    const float* sbias = (const float*)(smem + M2_BI);

    u32 aH[4][4], aL[4][4];
    {
        u32 arow = (u32)(w * 16 + (l & 15)) * XP + (u32)(l >> 4) * 16;
#pragma unroll
        for (int ks = 0; ks < 4; ks++) {
            ldmx4(aH[ks][0], aH[ks][1], aH[ks][2], aH[ks][3], sb + M2_FH + arow + ks * 32);
            ldmx4(aL[ks][0], aL[ks][1], aL[ks][2], aL[ks][3], sb + M2_FL + arow + ks * 32);
        }
    }
    u32 brow = (u32)(l & 15) * PITCH;

    u32 h1H[2][4], h1L[2][4];
#pragma unroll
    for (int nc = 0; nc < 4; nc++) {
        float cA[4] = {0,0,0,0}, cB[4] = {0,0,0,0}, cC[4] = {0,0,0,0};
#pragma unroll
        for (int ks = 0; ks < 4; ks++) {
            u32 woff = (u32)(ks * 16) * PITCH + (u32)nc * 16 + brow;
            u32 wh0, wh1, wl0, wl1;
            ldmx2t(wh0, wh1, sb + M2_WH + woff);
            ldmx2t(wl0, wl1, sb + M2_WL + woff);
            mma16816(cA[0],cA[1],cA[2],cA[3], aH[ks][0],aH[ks][1],aH[ks][2],aH[ks][3], wh0, wh1);
            mma16816(cB[0],cB[1],cB[2],cB[3], aH[ks][0],aH[ks][1],aH[ks][2],aH[ks][3], wl0, wl1);
            mma16816(cC[0],cC[1],cC[2],cC[3], aL[ks][0],aL[ks][1],aL[ks][2],aL[ks][3], wh0, wh1);
        }
        float b0 = sbias[nc * 8 + 2 * tig], b1v = sbias[nc * 8 + 2 * tig + 1];
        float v0 = fmaxf(cA[0] + cB[0] + cC[0] + b0,  0.f);
        float v1 = fmaxf(cA[1] + cB[1] + cC[1] + b1v, 0.f);
        float v2 = fmaxf(cA[2] + cB[2] + cC[2] + b0,  0.f);
        float v3 = fmaxf(cA[3] + cB[3] + cC[3] + b1v, 0.f);
        u32 h01 = packh2(v0, v1), h23 = packh2(v2, v3);
        float2 f01 = __half22float2(*(__half2*)&h01), f23 = __half22float2(*(__half2*)&h23);
        int ks2 = nc >> 1, pos = (nc & 1) * 2;
        h1H[ks2][pos] = h01; h1H[ks2][pos + 1] = h23;
        h1L[ks2][pos]     = packh2(v0 - f01.x, v1 - f01.y);
        h1L[ks2][pos + 1] = packh2(v2 - f23.x, v3 - f23.y);
    }

    u32 h2H[2][4], h2L[2][4];
#pragma unroll
    for (int nc = 0; nc < 4; nc++) {
        float cA[4] = {0,0,0,0}, cB[4] = {0,0,0,0}, cC[4] = {0,0,0,0};
#pragma unroll
        for (int ks = 0; ks < 2; ks++) {
            u32 woff = (u32)(64 + ks * 16) * PITCH + (u32)nc * 16 + brow;
            u32 wh0, wh1, wl0, wl1;
            ldmx2t(wh0, wh1, sb + M2_WH + woff);
            ldmx2t(wl0, wl1, sb + M2_WL + woff);
            mma16816(cA[0],cA[1],cA[2],cA[3], h1H[ks][0],h1H[ks][1],h1H[ks][2],h1H[ks][3], wh0, wh1);
            mma16816(cB[0],cB[1],cB[2],cB[3], h1H[ks][0],h1H[ks][1],h1H[ks][2],h1H[ks][3], wl0, wl1);
            mma16816(cC[0],cC[1],cC[2],cC[3], h1L[ks][0],h1L[ks][1],h1L[ks][2],h1L[ks][3], wh0, wh1);
        }
        float b0 = sbias[32 + nc * 8 + 2 * tig], b1v = sbias[32 + nc * 8 + 2 * tig + 1];
        float v0 = fmaxf(cA[0] + cB[0] + cC[0] + b0,  0.f);
        float v1 = fmaxf(cA[1] + cB[1] + cC[1] + b1v, 0.f);
        float v2 = fmaxf(cA[2] + cB[2] + cC[2] + b0,  0.f);
        float v3 = fmaxf(cA[3] + cB[3] + cC[3] + b1v, 0.f);
        u32 h01 = packh2(v0, v1), h23 = packh2(v2, v3);
        float2 f01 = __half22float2(*(__half2*)&h01), f23 = __half22float2(*(__half2*)&h23);
        int ks2 = nc >> 1, pos = (nc & 1) * 2;
        h2H[ks2][pos] = h01; h2H[ks2][pos + 1] = h23;
        h2L[ks2][pos]     = packh2(v0 - f01.x, v1 - f01.y);
        h2L[ks2][pos + 1] = packh2(v2 - f23.x, v3 - f23.y);
    }

    float nxA = 0.f, nxB = 0.f;
    int rg = row0 + w * 16 + g;
    float sc = isX ? LOG2E : 1.f;
#pragma unroll
    for (int nc = 0; nc < 4; nc++) {
        float cA[4] = {0,0,0,0}, cB[4] = {0,0,0,0}, cC[4] = {0,0,0,0};
#pragma unroll
        for (int ks = 0; ks < 2; ks++) {
            u32 woff = (u32)(96 + ks * 16) * PITCH + (u32)nc * 16 + brow;
            u32 wh0, wh1, wl0, wl1;
            ldmx2t(wh0, wh1, sb + M2_WH + woff);
            ldmx2t(wl0, wl1, sb + M2_WL + woff);
            mma16816(cA[0],cA[1],cA[2],cA[3], h2H[ks][0],h2H[ks][1],h2H[ks][2],h2H[ks][3], wh0, wh1);
            mma16816(cB[0],cB[1],cB[2],cB[3], h2H[ks][0],h2H[ks][1],h2H[ks][2],h2H[ks][3], wl0, wl1);
            mma16816(cC[0],cC[1],cC[2],cC[3], h2L[ks][0],h2L[ks][1],h2L[ks][2],h2L[ks][3], wh0, wh1);
        }
        float b0 = sbias[64 + nc * 8 + 2 * tig], b1v = sbias[64 + nc * 8 + 2 * tig + 1];
        float v0 = fmaxf(cA[0] + cB[0] + cC[0] + b0,  0.f);
        float v1 = fmaxf(cA[1] + cB[1] + cC[1] + b1v, 0.f);
        float v2 = fmaxf(cA[2] + cB[2] + cC[2] + b0,  0.f);
        float v3 = fmaxf(cA[3] + cB[3] + cC[3] + b1v, 0.f);
        nxA += v0 * v0 + v1 * v1;
        nxB += v2 * v2 + v3 * v3;
        float s0 = v0 * sc, s1 = v1 * sc, s2 = v2 * sc, s3 = v3 * sc;
        u32 h01 = packh2(s0, s1), h23 = packh2(s2, s3);
        float2 f01 = __half22float2(*(__half2*)&h01), f23 = __half22float2(*(__half2*)&h23);
        u32 l01 = packh2(s0 - f01.x, s1 - f01.y), l23 = packh2(s2 - f23.x, s3 - f23.y);
        ((u32*)g_Fhi)[rg * 16 + nc * 4 + tig]       = h01;
        ((u32*)g_Fhi)[(rg + 8) * 16 + nc * 4 + tig] = h23;
        ((u32*)g_Flo)[rg * 16 + nc * 4 + tig]       = l01;
        ((u32*)g_Flo)[(rg + 8) * 16 + nc * 4 + tig] = l23;
    }
    nxA += __shfl_xor_sync(0xffffffffu, nxA, 1);
    nxA += __shfl_xor_sync(0xffffffffu, nxA, 2);
    nxB += __shfl_xor_sync(0xffffffffu, nxB, 1);
    nxB += __shfl_xor_sync(0xffffffffu, nxB, 2);
    if (tig == 0) {
        g_Fn[rg]     = -HALF_L2E * nxA;
        g_Fn[rg + 8] = -HALF_L2E * nxB;
    }
}

// ---------------- kernel 2: HMMA flash kernel (fused-chain MMA1, ones-col denominator) ----------------
__global__ __launch_bounds__(THREADS)
void dist_kernel()
{
    extern __shared__ char smem[];
    u32 sb = smem_u32(smem);
    int tid = threadIdx.x, w = tid >> 5, l = tid & 31;
    int g = l >> 2, tig = l & 3;
    int row0 = blockIdx.x * TTM;
    int m0   = blockIdx.y * (M_ / MSPLIT);

    // ---- preamble: A tile (2 chunks/thread) + tile0 of B/V/cy + ones block
    {
#pragma unroll
        for (int q = 0; q < 2; q++) {
            int id = tid + q * THREADS, r = id >> 2, c = id & 3;
            *(uint4*)(smem + S_AHI + r * PITCH + c * 16) = *(const uint4*)(g_Fhi + (size_t)(row0 + r) * H_ + c * 8);
            *(uint4*)(smem + S_ALO + r * PITCH + c * 16) = *(const uint4*)(g_Flo + (size_t)(row0 + r) * H_ + c * 8);
        }
        { int r = tid >> 2, c = tid & 3;
          *(uint4*)(smem + S_B + r * PITCH + c * 16)         = *(const uint4*)(g_Fhi + (size_t)(N_ + m0 + r) * H_ + c * 8);
          *(uint4*)(smem + S_B + 10240 + r * PITCH + c * 16) = *(const uint4*)(g_Flo + (size_t)(N_ + m0 + r) * H_ + c * 8); }
        if (tid < 128)      *(uint4*)(smem + S_V + tid * 16)            = *(const uint4*)(g_Vhi + (size_t)(m0 + tid) * T_);
        else if (tid < 256) *(uint4*)(smem + S_V + 2048 + (tid-128)*16) = *(const uint4*)(g_Vlo + (size_t)(m0 + tid - 128) * T_);
        else if (tid < 384) ((float*)(smem + S_CY))[tid - 256] = g_Fn[N_ + m0 + tid - 256];
        else if (tid < 416) {   // ones block: 32 rows x [1.0h, 0 x7]
            uint4 one = make_uint4(0x00003C00u, 0u, 0u, 0u);
            *(uint4*)(smem + S_VONE + (tid - 384) * 16) = one;
        }
    }
    __syncthreads();

    // ---- persistent A fragments + constant ones B-fragment
    u32 aH0[4], aH1[4], aL0[4], aL1[4];
    u32 vo0, vo1;
    u32 vArow = (u32)(l & 15) * 16;
    {
        u32 arow = (u32)(w * 16 + (l & 15)) * PITCH + (u32)(l >> 4) * 16;
        ldmx4(aH0[0], aH0[1], aH0[2], aH0[3], sb + S_AHI + arow);
        ldmx4(aH1[0], aH1[1], aH1[2], aH1[3], sb + S_AHI + arow + 32);
        ldmx4(aL0[0], aL0[1], aL0[2], aL0[3], sb + S_ALO + arow);
        ldmx4(aL1[0], aL1[1], aL1[2], aL1[3], sb + S_ALO + arow + 32);
        ldmx2t(vo0, vo1, sb + S_VONE + vArow);
    }

    float cx0 = g_Fn[row0 + w * 16 + g];
    float cx1 = g_Fn[row0 + w * 16 + g + 8];

    float oA0 = 0.f, oA1 = 0.f, oA2 = 0.f, oA3 = 0.f;   // P@Vhi chain
    float oB0 = 0.f, oB1 = 0.f, oB2 = 0.f, oB3 = 0.f;   // P@Vlo chain
    float oS0 = 0.f, oS1 = 0.f, oS2 = 0.f, oS3 = 0.f;   // P@ones chain (col8 = rowsum @ tig0)

    u32 bArow = (u32)(l & 7) * PITCH + (u32)(l >> 3) * 16;

#pragma unroll 1
    for (int i = 0; i < TILES; i++) {
        uint4 nbh, nbl, nv; float ncy = 0.f;
        bool pf = (i + 1 < TILES);
        if (pf) {
            int mb = m0 + (i + 1) * TTN;
            { int r = tid >> 2, c = tid & 3;
              nbh = *(const uint4*)(g_Fhi + (size_t)(N_ + mb + r) * H_ + c * 8);
              nbl = *(const uint4*)(g_Flo + (size_t)(N_ + mb + r) * H_ + c * 8); }
            if (tid < 128)      nv  = *(const uint4*)(g_Vhi + (size_t)(mb + tid) * T_);
            else if (tid < 256) nv  = *(const uint4*)(g_Vlo + (size_t)(mb + tid - 128) * T_);
            else if (tid < 384) ncy = g_Fn[N_ + mb + tid - 256];
        }

        int ib = i & 1;
        u32 Bhi = sb + S_B + ib * 20480, Blo = Bhi + 10240;
        u32 Vhi = sb + S_V + ib * 4096,  Vlo = Vhi + 2048;
        const float* cyb = (const float*)(smem + S_CY + ib * 512);

#pragma unroll 1
        for (int s = 0; s < 8; s++) {
            u32 aP[4];
#pragma unroll
            for (int hhalf = 0; hhalf < 2; hhalf++) {
                int nc = 2 * s + hhalf;
                u32 bh[4], bl[4];
                ldmx4(bh[0], bh[1], bh[2], bh[3], Bhi + (u32)nc * (8 * PITCH) + bArow);
                ldmx4(bl[0], bl[1], bl[2], bl[3], Blo + (u32)nc * (8 * PITCH) + bArow);

                // single fused accumulation chain (6 MMAs)
                float c0 = 0.f, c1 = 0.f, c2 = 0.f, c3 = 0.f;
                mma16816(c0, c1, c2, c3, aH0[0], aH0[1], aH0[2], aH0[3], bh[0], bh[1]);
                mma16816(c0, c1, c2, c3, aH1[0], aH1[1], aH1[2], aH1[3], bh[2], bh[3]);
                mma16816(c0, c1, c2, c3, aL0[0], aL0[1], aL0[2], aL0[3], bh[0], bh[1]);
                mma16816(c0, c1, c2, c3, aL1[0], aL1[1], aL1[2], aL1[3], bh[2], bh[3]);
                mma16816(c0, c1, c2, c3, aH0[0], aH0[1], aH0[2], aH0[3], bl[0], bl[1]);
                mma16816(c0, c1, c2, c3, aH1[0], aH1[1], aH1[2], aH1[3], bl[2], bl[3]);

                float2 cy = *(const float2*)(cyb + nc * 8 + 2 * tig);
                float cxy0 = cx0 + cy.x, cxy1 = cx0 + cy.y;
                float cxy2 = cx1 + cy.x, cxy3 = cx1 + cy.y;
                float k0 = ex2f(fminf(c0 + cxy0, 0.f));
                float k1 = ex2f(fminf(c1 + cxy1, 0.f));
                float k2 = ex2f(fminf(c2 + cxy2, 0.f));
                float k3 = ex2f(fminf(c3 + cxy3, 0.f));

                aP[2 * hhalf]     = packh2(k0, k1);
                aP[2 * hhalf + 1] = packh2(k2, k3);
            }

            u32 vh[2], vl[2];
            ldmx2t(vh[0], vh[1], Vhi + (u32)s * 256 + vArow);
            ldmx2t(vl[0], vl[1], Vlo + (u32)s * 256 + vArow);
            mma16816(oA0, oA1, oA2, oA3, aP[0], aP[1], aP[2], aP[3], vh[0], vh[1]);
            mma16816(oS0, oS1, oS2, oS3, aP[0], aP[1], aP[2], aP[3], vo0, vo1);
            mma16816(oB0, oB1, oB2, oB3, aP[0], aP[1], aP[2], aP[3], vl[0], vl[1]);
        }

        if (pf) {
            int ib2 = (i + 1) & 1;
            { int r = tid >> 2, c = tid & 3;
              *(uint4*)(smem + S_B + ib2 * 20480 + r * PITCH + c * 16)         = nbh;
              *(uint4*)(smem + S_B + ib2 * 20480 + 10240 + r * PITCH + c * 16) = nbl; }
            if (tid < 128)      *(uint4*)(smem + S_V + ib2 * 4096 + tid * 16)              = nv;
            else if (tid < 256) *(uint4*)(smem + S_V + ib2 * 4096 + 2048 + (tid-128) * 16) = nv;
            else if (tid < 384) ((float*)(smem + S_CY + ib2 * 512))[tid - 256] = ncy;
        }
        __syncthreads();
    }

    float o0 = oA0 + oB0, o1 = oA1 + oB1, o2 = oA2 + oB2, o3 = oA3 + oB3;

    int ra = row0 + w * 16 + g;
    int rb = ra + 8;
    int by = blockIdx.y;
    g_part[IDXP(by, 2 * tig,     ra)] = o0;
    g_part[IDXP(by, 2 * tig + 1, ra)] = o1;
    g_part[IDXP(by, 2 * tig,     rb)] = o2;
    g_part[IDXP(by, 2 * tig + 1, rb)] = o3;
    if (tig == 0) { g_part[IDXP(by, T_, ra)] = oS0; g_part[IDXP(by, T_, rb)] = oS2; }
}

// ---------------- kernel 3: combine partials, normalize (coalesced) ----------------
__global__ __launch_bounds__(256)
void reduce_kernel(float* __restrict__ out)
{
    int row = blockIdx.x * 256 + threadIdx.x;   // N_ rows
    float sk = 0.f;
#pragma unroll
    for (int c = 0; c < MSPLIT; c++) sk += g_part[IDXP(c, T_, row)];
    float inv = 1.f / sk;
    float o[T_];
#pragma unroll
    for (int t = 0; t < T_; t++) {
        float st = 0.f;
#pragma unroll
        for (int c = 0; c < MSPLIT; c++) st += g_part[IDXP(c, t, row)];
        o[t] = st * inv;
    }
    float4* dst = (float4*)(out + (size_t)row * T_);
    dst[0] = make_float4(o[0], o[1], o[2], o[3]);
    dst[1] = make_float4(o[4], o[5], o[6], o[7]);
}

// ---------------- launch ----------------
extern "C" void kernel_launch(void* const* d_in, const int* in_sizes, int n_in,
                              void* d_out, int out_size)
{
    (void)in_sizes; (void)n_in; (void)out_size;
    const float* X  = (const float*)d_in[0];
    const float* Y  = (const float*)d_in[1];
    const float* Yt = (const float*)d_in[2];
    const float* W1 = (const float*)d_in[3];
    const float* b1 = (const float*)d_in[4];
    const float* W2 = (const float*)d_in[5];
    const float* b2 = (const float*)d_in[6];
    const float* W3 = (const float*)d_in[7];
    const float* b3 = (const float*)d_in[8];
    float* out = (float*)d_out;

    cudaFuncSetAttribute(mlp2_kernel, cudaFuncAttributeMaxDynamicSharedMemorySize, M2_TOTAL);
    cudaFuncSetAttribute(dist_kernel, cudaFuncAttributeMaxDynamicSharedMemorySize, SMEM_TOTAL);

    mlp2_kernel<<<MLP2BLKS + (M_ * T_) / 256, 256, M2_TOTAL>>>(X, Y, Yt, W1, b1, W2, b2, W3, b3);
    dist_kernel<<<dim3(N_ / TTM, MSPLIT), THREADS, SMEM_TOTAL>>>();
    reduce_kernel<<<N_ / 256, 256>>>(out);
}

// round 17
// speedup vs baseline: 1.5597x; 1.0438x over previous
#include <cuda_runtime.h>
#include <cuda_fp16.h>
#include <cstdint>

// Problem constants
#define N_  8192
#define M_  8192
#define D_  64
#define H_  32
#define T_  8

#define MSPLIT 4
#define TTM    256                      // X rows per CTA (dist)
#define TTN    128                      // Y rows per tile iter
#define TILES  ((M_ / MSPLIT) / TTN)    // 16
#define THREADS 512
#define LOG2E     1.4426950408889634f
#define HALF_L2E  0.7213475204444817f

typedef unsigned long long u64;
typedef unsigned int u32;

// ---------------- global scratch ----------------
__device__ __half g_Fhi[(N_ + M_) * H_];   // X rows pre-scaled by log2e; Y rows raw
__device__ __half g_Flo[(N_ + M_) * H_];
__device__ float  g_Fn[N_ + M_];           // -0.5*log2e*||f||^2
__device__ __half g_Vhi[M_ * T_];          // Yt hi, [j][t]
__device__ __half g_Vlo[M_ * T_];
__device__ u32    g_arrive[N_ / TTM];      // per-row-tile arrival counters (reset each launch)
// partials transposed: [chunk][t(0..8)][row]
__device__ float  g_part[MSPLIT * (T_ + 1) * N_];
#define IDXP(c, t, row) ((((c) * (T_ + 1)) + (t)) * N_ + (row))

// ---------------- helpers ----------------
__device__ __forceinline__ u32 smem_u32(const void* p) {
    u32 a; asm("{ .reg .u64 t; cvta.to.shared.u64 t, %1; cvt.u32.u64 %0, t; }" : "=r"(a) : "l"(p));
    return a;
}
__device__ __forceinline__ float ex2f(float x) {
    float r; asm("ex2.approx.ftz.f32 %0, %1;" : "=f"(r) : "f"(x)); return r;
}
__device__ __forceinline__ void ldmx4(u32& r0, u32& r1, u32& r2, u32& r3, u32 addr) {
    asm volatile("ldmatrix.sync.aligned.m8n8.x4.shared.b16 {%0,%1,%2,%3}, [%4];"
        : "=r"(r0), "=r"(r1), "=r"(r2), "=r"(r3) : "r"(addr));
}
__device__ __forceinline__ void ldmx2t(u32& r0, u32& r1, u32 addr) {
    asm volatile("ldmatrix.sync.aligned.m8n8.x2.trans.shared.b16 {%0,%1}, [%2];"
        : "=r"(r0), "=r"(r1) : "r"(addr));
}
__device__ __forceinline__ void mma16816(float& c0, float& c1, float& c2, float& c3,
                                         u32 a0, u32 a1, u32 a2, u32 a3, u32 b0, u32 b1) {
    asm volatile("mma.sync.aligned.m16n8k16.row.col.f32.f16.f16.f32 "
        "{%0,%1,%2,%3},{%4,%5,%6,%7},{%8,%9},{%0,%1,%2,%3};"
        : "+f"(c0), "+f"(c1), "+f"(c2), "+f"(c3)
        : "r"(a0), "r"(a1), "r"(a2), "r"(a3), "r"(b0), "r"(b1));
}
__device__ __forceinline__ u32 packh2(float a, float b) {
    __half2 h = __floats2half2_rn(a, b);
    return *(u32*)&h;
}

// ---------------- dist SMEM layout ----------------
#define PITCH   80                      // 64B data + 16B pad -> conflict-free ldmatrix
#define S_AHI   0                       // 256 rows * 80B
#define S_ALO   20480
#define S_B     40960                   // [stage][hi/lo]: stage*20480, lo +10240
#define S_V     81920                   // [stage][hi/lo]: stage*4096, lo +2048
#define S_CY    90112                   // [stage] 512B, 2 stages
#define S_VONE  91136                   // constant ones block, 512B
#define S_RED   91648                   // arrival-count broadcast word (16B)
#define SMEM_TOTAL 91664

// ---------------- mlp2 SMEM layout (64 rows per CTA) ----------------
#define XP      144                     // X row pitch bytes (128B data + 16 pad)
#define M2_FH   0                       // 64*144 = 9216
#define M2_FL   9216
#define M2_WH   18432                   // 128 rows (W1:0-63, W2:64-95, W3:96-127) * 80B
#define M2_WL   28672
#define M2_BI   38912                   // 96 floats
#define M2_TOTAL 39296

// ---------------- kernel 1: MLP on tensor cores (64 rows/CTA, 256 thr) + V prep + reset ----------------
#define MLP2BLKS ((N_ + M_) / 64)       // 256
#define VPREPBLKS ((M_ * T_) / 2048)    // 32
__global__ __launch_bounds__(256)
void mlp2_kernel(const float* __restrict__ X, const float* __restrict__ Y,
                 const float* __restrict__ Yt,
                 const float* __restrict__ W1, const float* __restrict__ b1,
                 const float* __restrict__ W2, const float* __restrict__ b2,
                 const float* __restrict__ W3, const float* __restrict__ b3)
{
    if (blockIdx.x >= MLP2BLKS) {           // tail blocks: build V hi/lo (vectorized) + reset counters
        int tv = blockIdx.x - MLP2BLKS;
        if (tv == 0 && threadIdx.x < (N_ / TTM)) g_arrive[threadIdx.x] = 0;
        int vi = tv * 256 + threadIdx.x;    // 8 values per thread
        const float4* Yt4 = (const float4*)Yt;
        float4 v0 = Yt4[vi * 2], v1 = Yt4[vi * 2 + 1];
        u32 h0 = packh2(v0.x, v0.y), h1 = packh2(v0.z, v0.w);
        u32 h2 = packh2(v1.x, v1.y), h3 = packh2(v1.z, v1.w);
        float2 f0 = __half22float2(*(__half2*)&h0), f1 = __half22float2(*(__half2*)&h1);
        float2 f2 = __half22float2(*(__half2*)&h2), f3 = __half22float2(*(__half2*)&h3);
        ((uint4*)g_Vhi)[vi] = make_uint4(h0, h1, h2, h3);
        ((uint4*)g_Vlo)[vi] = make_uint4(
            packh2(v0.x - f0.x, v0.y - f0.y), packh2(v0.z - f1.x, v0.w - f1.y),
            packh2(v1.x - f2.x, v1.y - f2.y), packh2(v1.z - f3.x, v1.w - f3.y));
        return;
    }

    extern __shared__ char smem[];
    u32 sb = smem_u32(smem);
    int tid = threadIdx.x, w = tid >> 5, l = tid & 31;
    int g = l >> 2, tig = l & 3;
    int row0 = blockIdx.x * 64;
    bool isX = (row0 < N_);
    const float* src = isX ? (X + (size_t)row0 * D_) : (Y + (size_t)(row0 - N_) * D_);

    // ---- load X tile [64 x 64] f32 -> hi/lo f16 (all 8 warps)
#pragma unroll
    for (int q = 0; q < 4; q++) {
        int idx = q * 256 + tid;            // 1024 float4
        int r = idx >> 4, c4 = idx & 15;
        float4 v = ((const float4*)src)[idx];
        float hx = __half2float(__float2half_rn(v.x));
        float hy = __half2float(__float2half_rn(v.y));
        float hz = __half2float(__float2half_rn(v.z));
        float hw = __half2float(__float2half_rn(v.w));
        u32* ph = (u32*)(smem + M2_FH + r * XP + c4 * 8);
        u32* pl = (u32*)(smem + M2_FL + r * XP + c4 * 8);
        ph[0] = packh2(v.x, v.y);        ph[1] = packh2(v.z, v.w);
        pl[0] = packh2(v.x - hx, v.y - hy); pl[1] = packh2(v.z - hz, v.w - hw);
    }
    // ---- weights [k][n] hi/lo (all 8 warps)
#pragma unroll
    for (int q = 0; q < 2; q++) {           // W1: 512 float4
        int idx = q * 256 + tid;
        int r = idx >> 3, c4 = idx & 7;
        float4 v = ((const float4*)W1)[idx];
        float hx = __half2float(__float2half_rn(v.x));
        float hy = __half2float(__float2half_rn(v.y));
        float hz = __half2float(__float2half_rn(v.z));
        float hw = __half2float(__float2half_rn(v.w));
        u32* ph = (u32*)(smem + M2_WH + r * PITCH + c4 * 8);
        u32* pl = (u32*)(smem + M2_WL + r * PITCH + c4 * 8);
        ph[0] = packh2(v.x, v.y);        ph[1] = packh2(v.z, v.w);
        pl[0] = packh2(v.x - hx, v.y - hy); pl[1] = packh2(v.z - hz, v.w - hw);
    }
    {                                        // W2 + W3: 256+256 float4
        const float4* Wsrc[2] = { (const float4*)W2, (const float4*)W3 };
#pragma unroll
        for (int m = 0; m < 2; m++) {
            int r = 64 + m * 32 + (tid >> 3), c4 = tid & 7;
            float4 v = Wsrc[m][tid];
            float hx = __half2float(__float2half_rn(v.x));
            float hy = __half2float(__float2half_rn(v.y));
            float hz = __half2float(__float2half_rn(v.z));
            float hw = __half2float(__float2half_rn(v.w));
            u32* ph = (u32*)(smem + M2_WH + r * PITCH + c4 * 8);
            u32* pl = (u32*)(smem + M2_WL + r * PITCH + c4 * 8);
            ph[0] = packh2(v.x, v.y);        ph[1] = packh2(v.z, v.w);
            pl[0] = packh2(v.x - hx, v.y - hy); pl[1] = packh2(v.z - hz, v.w - hw);
        }
    }
    if (tid < 96) {
        float bv = (tid < 32) ? b1[tid] : (tid < 64) ? b2[tid - 32] : b3[tid - 64];
        ((float*)(smem + M2_BI))[tid] = bv;
    }
    __syncthreads();

    if (w >= 4) return;                      // warps 4-7: prologue only

    const float* sbias = (const float*)(smem + M2_BI);

    // ---- A frags from X (4 k-steps); warp w owns rows [w*16, w*16+16)
    u32 aH[4][4], aL[4][4];
    {
        u32 arow = (u32)(w * 16 + (l & 15)) * XP + (u32)(l >> 4) * 16;
#pragma unroll
        for (int ks = 0; ks < 4; ks++) {
            ldmx4(aH[ks][0], aH[ks][1], aH[ks][2], aH[ks][3], sb + M2_FH + arow + ks * 32);
            ldmx4(aL[ks][0], aL[ks][1], aL[ks][2], aL[ks][3], sb + M2_FL + arow + ks * 32);
        }
    }
    u32 brow = (u32)(l & 15) * PITCH;

    // ---- layer 1
    u32 h1H[2][4], h1L[2][4];
#pragma unroll
    for (int nc = 0; nc < 4; nc++) {
        float cA[4] = {0,0,0,0}, cB[4] = {0,0,0,0}, cC[4] = {0,0,0,0};
#pragma unroll
        for (int ks = 0; ks < 4; ks++) {
            u32 woff = (u32)(ks * 16) * PITCH + (u32)nc * 16 + brow;
            u32 wh0, wh1, wl0, wl1;
            ldmx2t(wh0, wh1, sb + M2_WH + woff);
            ldmx2t(wl0, wl1, sb + M2_WL + woff);
            mma16816(cA[0],cA[1],cA[2],cA[3], aH[ks][0],aH[ks][1],aH[ks][2],aH[ks][3], wh0, wh1);
            mma16816(cB[0],cB[1],cB[2],cB[3], aH[ks][0],aH[ks][1],aH[ks][2],aH[ks][3], wl0, wl1);
            mma16816(cC[0],cC[1],cC[2],cC[3], aL[ks][0],aL[ks][1],aL[ks][2],aL[ks][3], wh0, wh1);
        }
        float b0 = sbias[nc * 8 + 2 * tig], b1v = sbias[nc * 8 + 2 * tig + 1];
        float v0 = fmaxf(cA[0] + cB[0] + cC[0] + b0,  0.f);
        float v1 = fmaxf(cA[1] + cB[1] + cC[1] + b1v, 0.f);
        float v2 = fmaxf(cA[2] + cB[2] + cC[2] + b0,  0.f);
        float v3 = fmaxf(cA[3] + cB[3] + cC[3] + b1v, 0.f);
        u32 h01 = packh2(v0, v1), h23 = packh2(v2, v3);
        float2 f01 = __half22float2(*(__half2*)&h01), f23 = __half22float2(*(__half2*)&h23);
        int ks2 = nc >> 1, pos = (nc & 1) * 2;
        h1H[ks2][pos] = h01; h1H[ks2][pos + 1] = h23;
        h1L[ks2][pos]     = packh2(v0 - f01.x, v1 - f01.y);
        h1L[ks2][pos + 1] = packh2(v2 - f23.x, v3 - f23.y);
    }

    // ---- layer 2
    u32 h2H[2][4], h2L[2][4];
#pragma unroll
    for (int nc = 0; nc < 4; nc++) {
        float cA[4] = {0,0,0,0}, cB[4] = {0,0,0,0}, cC[4] = {0,0,0,0};
#pragma unroll
        for (int ks = 0; ks < 2; ks++) {
            u32 woff = (u32)(64 + ks * 16) * PITCH + (u32)nc * 16 + brow;
            u32 wh0, wh1, wl0, wl1;
            ldmx2t(wh0, wh1, sb + M2_WH + woff);
            ldmx2t(wl0, wl1, sb + M2_WL + woff);
            mma16816(cA[0],cA[1],cA[2],cA[3], h1H[ks][0],h1H[ks][1],h1H[ks][2],h1H[ks][3], wh0, wh1);
            mma16816(cB[0],cB[1],cB[2],cB[3], h1H[ks][0],h1H[ks][1],h1H[ks][2],h1H[ks][3], wl0, wl1);
            mma16816(cC[0],cC[1],cC[2],cC[3], h1L[ks][0],h1L[ks][1],h1L[ks][2],h1L[ks][3], wh0, wh1);
        }
        float b0 = sbias[32 + nc * 8 + 2 * tig], b1v = sbias[32 + nc * 8 + 2 * tig + 1];
        float v0 = fmaxf(cA[0] + cB[0] + cC[0] + b0,  0.f);
        float v1 = fmaxf(cA[1] + cB[1] + cC[1] + b1v, 0.f);
        float v2 = fmaxf(cA[2] + cB[2] + cC[2] + b0,  0.f);
        float v3 = fmaxf(cA[3] + cB[3] + cC[3] + b1v, 0.f);
        u32 h01 = packh2(v0, v1), h23 = packh2(v2, v3);
        float2 f01 = __half22float2(*(__half2*)&h01), f23 = __half22float2(*(__half2*)&h23);
        int ks2 = nc >> 1, pos = (nc & 1) * 2;
        h2H[ks2][pos] = h01; h2H[ks2][pos + 1] = h23;
        h2L[ks2][pos]     = packh2(v0 - f01.x, v1 - f01.y);
        h2L[ks2][pos + 1] = packh2(v2 - f23.x, v3 - f23.y);
    }

    // ---- layer 3 + epilogue
    float nxA = 0.f, nxB = 0.f;
    int rg = row0 + w * 16 + g;
    float sc = isX ? LOG2E : 1.f;
#pragma unroll
    for (int nc = 0; nc < 4; nc++) {
        float cA[4] = {0,0,0,0}, cB[4] = {0,0,0,0}, cC[4] = {0,0,0,0};
#pragma unroll
        for (int ks = 0; ks < 2; ks++) {
            u32 woff = (u32)(96 + ks * 16) * PITCH + (u32)nc * 16 + brow;
            u32 wh0, wh1, wl0, wl1;
            ldmx2t(wh0, wh1, sb + M2_WH + woff);
            ldmx2t(wl0, wl1, sb + M2_WL + woff);
            mma16816(cA[0],cA[1],cA[2],cA[3], h2H[ks][0],h2H[ks][1],h2H[ks][2],h2H[ks][3], wh0, wh1);
            mma16816(cB[0],cB[1],cB[2],cB[3], h2H[ks][0],h2H[ks][1],h2H[ks][2],h2H[ks][3], wl0, wl1);
            mma16816(cC[0],cC[1],cC[2],cC[3], h2L[ks][0],h2L[ks][1],h2L[ks][2],h2L[ks][3], wh0, wh1);
        }
        float b0 = sbias[64 + nc * 8 + 2 * tig], b1v = sbias[64 + nc * 8 + 2 * tig + 1];
        float v0 = fmaxf(cA[0] + cB[0] + cC[0] + b0,  0.f);
        float v1 = fmaxf(cA[1] + cB[1] + cC[1] + b1v, 0.f);
        float v2 = fmaxf(cA[2] + cB[2] + cC[2] + b0,  0.f);
        float v3 = fmaxf(cA[3] + cB[3] + cC[3] + b1v, 0.f);
        nxA += v0 * v0 + v1 * v1;
        nxB += v2 * v2 + v3 * v3;
        float s0 = v0 * sc, s1 = v1 * sc, s2 = v2 * sc, s3 = v3 * sc;
        u32 h01 = packh2(s0, s1), h23 = packh2(s2, s3);
        float2 f01 = __half22float2(*(__half2*)&h01), f23 = __half22float2(*(__half2*)&h23);
        u32 l01 = packh2(s0 - f01.x, s1 - f01.y), l23 = packh2(s2 - f23.x, s3 - f23.y);
        ((u32*)g_Fhi)[rg * 16 + nc * 4 + tig]       = h01;
        ((u32*)g_Fhi)[(rg + 8) * 16 + nc * 4 + tig] = h23;
        ((u32*)g_Flo)[rg * 16 + nc * 4 + tig]       = l01;
        ((u32*)g_Flo)[(rg + 8) * 16 + nc * 4 + tig] = l23;
    }
    nxA += __shfl_xor_sync(0xffffffffu, nxA, 1);
    nxA += __shfl_xor_sync(0xffffffffu, nxA, 2);
    nxB += __shfl_xor_sync(0xffffffffu, nxB, 1);
    nxB += __shfl_xor_sync(0xffffffffu, nxB, 2);
    if (tig == 0) {
        g_Fn[rg]     = -HALF_L2E * nxA;
        g_Fn[rg + 8] = -HALF_L2E * nxB;
    }
}

// ---------------- kernel 2: HMMA flash kernel + fused final reduction ----------------
__global__ __launch_bounds__(THREADS)
void dist_kernel(float* __restrict__ out)
{
    extern __shared__ char smem[];
    u32 sb = smem_u32(smem);
    int tid = threadIdx.x, w = tid >> 5, l = tid & 31;
    int g = l >> 2, tig = l & 3;
    int row0 = blockIdx.x * TTM;
    int m0   = blockIdx.y * (M_ / MSPLIT);

    // ---- preamble: A tile + tile0 of B/V/cy + ones block
    {
#pragma unroll
        for (int q = 0; q < 2; q++) {
            int id = tid + q * THREADS, r = id >> 2, c = id & 3;
            *(uint4*)(smem + S_AHI + r * PITCH + c * 16) = *(const uint4*)(g_Fhi + (size_t)(row0 + r) * H_ + c * 8);
            *(uint4*)(smem + S_ALO + r * PITCH + c * 16) = *(const uint4*)(g_Flo + (size_t)(row0 + r) * H_ + c * 8);
        }
        { int r = tid >> 2, c = tid & 3;
          *(uint4*)(smem + S_B + r * PITCH + c * 16)         = *(const uint4*)(g_Fhi + (size_t)(N_ + m0 + r) * H_ + c * 8);
          *(uint4*)(smem + S_B + 10240 + r * PITCH + c * 16) = *(const uint4*)(g_Flo + (size_t)(N_ + m0 + r) * H_ + c * 8); }
        if (tid < 128)      *(uint4*)(smem + S_V + tid * 16)            = *(const uint4*)(g_Vhi + (size_t)(m0 + tid) * T_);
        else if (tid < 256) *(uint4*)(smem + S_V + 2048 + (tid-128)*16) = *(const uint4*)(g_Vlo + (size_t)(m0 + tid - 128) * T_);
        else if (tid < 384) ((float*)(smem + S_CY))[tid - 256] = g_Fn[N_ + m0 + tid - 256];
        else if (tid < 416) {   // ones block: 32 rows x [1.0h, 0 x7]
            uint4 one = make_uint4(0x00003C00u, 0u, 0u, 0u);
            *(uint4*)(smem + S_VONE + (tid - 384) * 16) = one;
        }
    }
    __syncthreads();

    // ---- persistent A fragments + constant ones B-fragment
    u32 aH0[4], aH1[4], aL0[4], aL1[4];
    u32 vo0, vo1;
    u32 vArow = (u32)(l & 15) * 16;
    {
        u32 arow = (u32)(w * 16 + (l & 15)) * PITCH + (u32)(l >> 4) * 16;
        ldmx4(aH0[0], aH0[1], aH0[2], aH0[3], sb + S_AHI + arow);
        ldmx4(aH1[0], aH1[1], aH1[2], aH1[3], sb + S_AHI + arow + 32);
        ldmx4(aL0[0], aL0[1], aL0[2], aL0[3], sb + S_ALO + arow);
        ldmx4(aL1[0], aL1[1], aL1[2], aL1[3], sb + S_ALO + arow + 32);
        ldmx2t(vo0, vo1, sb + S_VONE + vArow);
    }

    float cx0 = g_Fn[row0 + w * 16 + g];
    float cx1 = g_Fn[row0 + w * 16 + g + 8];

    float oA0 = 0.f, oA1 = 0.f, oA2 = 0.f, oA3 = 0.f;   // P@Vhi chain
    float oB0 = 0.f, oB1 = 0.f, oB2 = 0.f, oB3 = 0.f;   // P@Vlo chain
    float oS0 = 0.f, oS1 = 0.f, oS2 = 0.f, oS3 = 0.f;   // P@ones chain (rowsum @ tig0)

    u32 bArow = (u32)(l & 7) * PITCH + (u32)(l >> 3) * 16;

#pragma unroll 1
    for (int i = 0; i < TILES; i++) {
        uint4 nbh, nbl, nv; float ncy = 0.f;
        bool pf = (i + 1 < TILES);
        if (pf) {
            int mb = m0 + (i + 1) * TTN;
            { int r = tid >> 2, c = tid & 3;
              nbh = *(const uint4*)(g_Fhi + (size_t)(N_ + mb + r) * H_ + c * 8);
              nbl = *(const uint4*)(g_Flo + (size_t)(N_ + mb + r) * H_ + c * 8); }
            if (tid < 128)      nv  = *(const uint4*)(g_Vhi + (size_t)(mb + tid) * T_);
            else if (tid < 256) nv  = *(const uint4*)(g_Vlo + (size_t)(mb + tid - 128) * T_);
            else if (tid < 384) ncy = g_Fn[N_ + mb + tid - 256];
        }

        int ib = i & 1;
        u32 Bhi = sb + S_B + ib * 20480, Blo = Bhi + 10240;
        u32 Vhi = sb + S_V + ib * 4096,  Vlo = Vhi + 2048;
        const float* cyb = (const float*)(smem + S_CY + ib * 512);

#pragma unroll 1
        for (int s = 0; s < 8; s++) {
            u32 aP[4];
#pragma unroll
            for (int hhalf = 0; hhalf < 2; hhalf++) {
                int nc = 2 * s + hhalf;
                u32 bh[4], bl[4];
                ldmx4(bh[0], bh[1], bh[2], bh[3], Bhi + (u32)nc * (8 * PITCH) + bArow);
                ldmx4(bl[0], bl[1], bl[2], bl[3], Blo + (u32)nc * (8 * PITCH) + bArow);

                float c0 = 0.f, c1 = 0.f, c2 = 0.f, c3 = 0.f;
                mma16816(c0, c1, c2, c3, aH0[0], aH0[1], aH0[2], aH0[3], bh[0], bh[1]);
                mma16816(c0, c1, c2, c3, aH1[0], aH1[1], aH1[2], aH1[3], bh[2], bh[3]);
                mma16816(c0, c1, c2, c3, aL0[0], aL0[1], aL0[2], aL0[3], bh[0], bh[1]);
                mma16816(c0, c1, c2, c3, aL1[0], aL1[1], aL1[2], aL1[3], bh[2], bh[3]);
                mma16816(c0, c1, c2, c3, aH0[0], aH0[1], aH0[2], aH0[3], bl[0], bl[1]);
                mma16816(c0, c1, c2, c3, aH1[0], aH1[1], aH1[2], aH1[3], bl[2], bl[3]);

                float2 cy = *(const float2*)(cyb + nc * 8 + 2 * tig);
                float k0 = ex2f(fminf(c0 + (cx0 + cy.x), 0.f));
                float k1 = ex2f(fminf(c1 + (cx0 + cy.y), 0.f));
                float k2 = ex2f(fminf(c2 + (cx1 + cy.x), 0.f));
                float k3 = ex2f(fminf(c3 + (cx1 + cy.y), 0.f));

                aP[2 * hhalf]     = packh2(k0, k1);
                aP[2 * hhalf + 1] = packh2(k2, k3);
            }

            u32 vh[2], vl[2];
            ldmx2t(vh[0], vh[1], Vhi + (u32)s * 256 + vArow);
            ldmx2t(vl[0], vl[1], Vlo + (u32)s * 256 + vArow);
            mma16816(oA0, oA1, oA2, oA3, aP[0], aP[1], aP[2], aP[3], vh[0], vh[1]);
            mma16816(oS0, oS1, oS2, oS3, aP[0], aP[1], aP[2], aP[3], vo0, vo1);
            mma16816(oB0, oB1, oB2, oB3, aP[0], aP[1], aP[2], aP[3], vl[0], vl[1]);
        }

        if (pf) {
            int ib2 = (i + 1) & 1;
            { int r = tid >> 2, c = tid & 3;
              *(uint4*)(smem + S_B + ib2 * 20480 + r * PITCH + c * 16)         = nbh;
              *(uint4*)(smem + S_B + ib2 * 20480 + 10240 + r * PITCH + c * 16) = nbl; }
            if (tid < 128)      *(uint4*)(smem + S_V + ib2 * 4096 + tid * 16)              = nv;
            else if (tid < 256) *(uint4*)(smem + S_V + ib2 * 4096 + 2048 + (tid-128) * 16) = nv;
            else if (tid < 384) ((float*)(smem + S_CY + ib2 * 512))[tid - 256] = ncy;
        }
        __syncthreads();
    }

    float o0 = oA0 + oB0, o1 = oA1 + oB1, o2 = oA2 + oB2, o3 = oA3 + oB3;

    int ra = row0 + w * 16 + g;
    int rb = ra + 8;
    int by = blockIdx.y;
    g_part[IDXP(by, 2 * tig,     ra)] = o0;
    g_part[IDXP(by, 2 * tig + 1, ra)] = o1;
    g_part[IDXP(by, 2 * tig,     rb)] = o2;
    g_part[IDXP(by, 2 * tig + 1, rb)] = o3;
    if (tig == 0) { g_part[IDXP(by, T_, ra)] = oS0; g_part[IDXP(by, T_, rb)] = oS2; }

    // ---- fused reduction: last of the 4 y-chunk CTAs for this row-tile does it
    __threadfence();
    u32* red = (u32*)(smem + S_RED);
    if (tid == 0) red[0] = atomicAdd(&g_arrive[blockIdx.x], 1u);
    __syncthreads();
    if (red[0] == MSPLIT - 1) {
        int row = row0 + (tid >> 1);        // 512 threads -> 256 rows x 2 halves
        int half = tid & 1;
        float sk = 0.f;
#pragma unroll
        for (int c = 0; c < MSPLIT; c++) sk += g_part[IDXP(c, T_, row)];
        float inv = 1.f / sk;
        float o[4];
#pragma unroll
        for (int t = 0; t < 4; t++) {
            float st = 0.f;
#pragma unroll
            for (int c = 0; c < MSPLIT; c++) st += g_part[IDXP(c, half * 4 + t, row)];
            o[t] = st * inv;
        }
        ((float4*)(out + (size_t)row * T_))[half] = make_float4(o[0], o[1], o[2], o[3]);
    }
}

// ---------------- launch ----------------
extern "C" void kernel_launch(void* const* d_in, const int* in_sizes, int n_in,
                              void* d_out, int out_size)
{
    (void)in_sizes; (void)n_in; (void)out_size;
    const float* X  = (const float*)d_in[0];
    const float* Y  = (const float*)d_in[1];
    const float* Yt = (const float*)d_in[2];
    const float* W1 = (const float*)d_in[3];
    const float* b1 = (const float*)d_in[4];
    const float* W2 = (const float*)d_in[5];
    const float* b2 = (const float*)d_in[6];
    const float* W3 = (const float*)d_in[7];
    const float* b3 = (const float*)d_in[8];
    float* out = (float*)d_out;

    cudaFuncSetAttribute(mlp2_kernel, cudaFuncAttributeMaxDynamicSharedMemorySize, M2_TOTAL);
    cudaFuncSetAttribute(dist_kernel, cudaFuncAttributeMaxDynamicSharedMemorySize, SMEM_TOTAL);

    mlp2_kernel<<<MLP2BLKS + VPREPBLKS, 256, M2_TOTAL>>>(X, Y, Yt, W1, b1, W2, b2, W3, b3);
    dist_kernel<<<dim3(N_ / TTM, MSPLIT), THREADS, SMEM_TOTAL>>>(out);
}